// round 3
// baseline (speedup 1.0000x reference)
#include <cuda_runtime.h>

#define BB 8
#define EE 64
#define MM 128
#define DD 256
#define HH 8
#define DKK 32
#define NPAIR (EE*EE)
#define SETHALF (BB*NPAIR*DD)
#define WCH 8

typedef unsigned long long ull;

// ---- packed fp32x2 helpers ----
__device__ __forceinline__ void fma2(ull &d, ull a, ull b) {
    asm("fma.rn.f32x2 %0, %1, %2, %0;" : "+l"(d) : "l"(a), "l"(b));
}
__device__ __forceinline__ ull bcast2(float x) {
    ull d;
    asm("mov.b64 %0, {%1, %1};" : "=l"(d) : "r"(__float_as_uint(x)));
    return d;
}
__device__ __forceinline__ float2 unpack2(ull v) {
    float2 r;
    asm("mov.b64 {%0, %1}, %2;" : "=f"(r.x), "=f"(r.y) : "l"(v));
    return r;
}

// ---------------- scratch ----------------
__device__ float g_msr[BB*MM*DD];
__device__ float g_q[2][BB*EE*DD];
__device__ float g_k[2][BB*MM*DD];
__device__ float g_v[2][BB*MM*DD];
__device__ float g_u[2][BB*HH*MM*DD];
__device__ float g_S[2][BB*HH*EE*MM];
__device__ float g_wm[2][BB*HH*MM*EE];   // softmax weights [s][b][h][m][j]
__device__ float g_usum[2][BB*DD];
__device__ int   g_cnt[BB*EE];
__device__ int   g_list[BB*EE*MM];

// ---------------- prep: gather msr + entity mention lists (fused) ----------------
__global__ void k_prep(const float* __restrict__ sentences,
                       const int* __restrict__ sent_ids,
                       const int* __restrict__ eid) {
    int blk = blockIdx.x;
    if (blk < BB * MM) {
        int b = blk >> 7, m = blk & 127;
        int sid = sent_ids[b*MM + m];
        const float4* src = (const float4*)(sentences + ((size_t)b*32 + sid)*DD);
        float4* dst = (float4*)(g_msr + ((size_t)b*MM + m)*DD);
        dst[threadIdx.x] = src[threadIdx.x];
    } else {
        int b = blk - BB * MM;
        int e = threadIdx.x;
        int cnt = 0;
        for (int m = 0; m < MM; m++)
            if (eid[b*MM + m] == e) g_list[(b*EE + e)*MM + cnt++] = m;
        g_cnt[b*EE + e] = cnt;
    }
}

// ---------------- six projections, 64x128 tiles, 8x4/thread, f32x2 ----------------
__global__ __launch_bounds__(256) void k_gemm_all(
    const float* __restrict__ entities, const float* __restrict__ mentions,
    const float* __restrict__ W_h, const float* __restrict__ b_h,
    const float* __restrict__ W_t, const float* __restrict__ b_t)
{
    __shared__ float a_sh[32][68];
    __shared__ float w_sh[32][128];
    int b = blockIdx.z;
    int y = blockIdx.y;
    int colTile = blockIdx.x;
    int job, rowTile;
    if (y < 2) { job = y; rowTile = 0; }
    else       { job = 2 + ((y - 2) >> 1); rowTile = (y - 2) & 1; }
    const float* A; const float* W; const float* bias; float* C; int rows;
    switch (job) {
      case 0:  A = entities; W = W_h;          bias = b_h;       C = g_q[0]; rows = EE; break;
      case 1:  A = entities; W = W_t;          bias = b_t;       C = g_q[1]; rows = EE; break;
      case 2:  A = g_msr;    W = W_h + 65536;  bias = b_h + 256; C = g_k[0]; rows = MM; break;
      case 3:  A = g_msr;    W = W_t + 65536;  bias = b_t + 256; C = g_k[1]; rows = MM; break;
      case 4:  A = mentions; W = W_h + 131072; bias = b_h + 512; C = g_v[0]; rows = MM; break;
      default: A = mentions; W = W_t + 131072; bias = b_t + 512; C = g_v[1]; rows = MM; break;
    }
    int row0 = rowTile * 64;
    int col0 = colTile * 128;
    const float* Ab = A + ((size_t)b * rows + row0) * DD;
    int tid = threadIdx.x;
    int rg = tid & 7;
    int cg = tid >> 3;
    ull acc[4][4];
    #pragma unroll
    for (int p = 0; p < 4; p++)
        #pragma unroll
        for (int c = 0; c < 4; c++) acc[p][c] = 0ull;

    for (int kc = 0; kc < 8; kc++) {
        int k0 = kc * 32;
        #pragma unroll
        for (int i = 0; i < 2; i++) {
            int f = tid * 2 + i;
            int r = f >> 3;
            int kq = (f & 7) * 4;
            float4 av = *(const float4*)(Ab + (size_t)r * DD + k0 + kq);
            a_sh[kq+0][r] = av.x; a_sh[kq+1][r] = av.y;
            a_sh[kq+2][r] = av.z; a_sh[kq+3][r] = av.w;
        }
        #pragma unroll
        for (int i = 0; i < 4; i++) {
            int idx = tid + i * 256;
            int kk = idx >> 5;
            int dq = (idx & 31) * 4;
            *(float4*)&w_sh[kk][dq] = *(const float4*)(W + (size_t)(k0 + kk) * DD + col0 + dq);
        }
        __syncthreads();
        #pragma unroll
        for (int kk = 0; kk < 32; kk++) {
            ulonglong2 A0 = *(const ulonglong2*)&a_sh[kk][rg * 8];
            ulonglong2 A1 = *(const ulonglong2*)&a_sh[kk][rg * 8 + 4];
            float4 wv = *(const float4*)&w_sh[kk][cg * 4];
            ull w0 = bcast2(wv.x), w1 = bcast2(wv.y), w2 = bcast2(wv.z), w3 = bcast2(wv.w);
            fma2(acc[0][0], A0.x, w0); fma2(acc[0][1], A0.x, w1);
            fma2(acc[0][2], A0.x, w2); fma2(acc[0][3], A0.x, w3);
            fma2(acc[1][0], A0.y, w0); fma2(acc[1][1], A0.y, w1);
            fma2(acc[1][2], A0.y, w2); fma2(acc[1][3], A0.y, w3);
            fma2(acc[2][0], A1.x, w0); fma2(acc[2][1], A1.x, w1);
            fma2(acc[2][2], A1.x, w2); fma2(acc[2][3], A1.x, w3);
            fma2(acc[3][0], A1.y, w0); fma2(acc[3][1], A1.y, w1);
            fma2(acc[3][2], A1.y, w2); fma2(acc[3][3], A1.y, w3);
        }
        __syncthreads();
    }
    float4 bi = *(const float4*)(bias + col0 + cg * 4);
    #pragma unroll
    for (int p = 0; p < 4; p++) {
        float2 c0 = unpack2(acc[p][0]), c1 = unpack2(acc[p][1]);
        float2 c2 = unpack2(acc[p][2]), c3 = unpack2(acc[p][3]);
        int re = row0 + rg * 8 + 2 * p;
        float4 oe = make_float4(c0.x + bi.x, c1.x + bi.y, c2.x + bi.z, c3.x + bi.w);
        float4 oo = make_float4(c0.y + bi.x, c1.y + bi.y, c2.y + bi.z, c3.y + bi.w);
        *(float4*)(C + ((size_t)b * rows + re)     * DD + col0 + cg * 4) = oe;
        *(float4*)(C + ((size_t)b * rows + re + 1) * DD + col0 + cg * 4) = oo;
    }
}

// ---------------- mid: uproj (256 blks) + usum (16 blks) + scores (128 blks) --------
__global__ __launch_bounds__(256) void k_mid(const float* __restrict__ W_h,
                                             const float* __restrict__ W_t)
{
    __shared__ __align__(16) char buf[33792];
    int blk = blockIdx.x;
    int tid = threadIdx.x;

    if (blk < 256) {
        int ct = blk & 1;
        int g = blk >> 1;
        int s = g >> 6, b = (g >> 3) & 7, h = g & 7;
        const float* Wo = (s ? W_t : W_h) + 3 * 65536 + h * DKK * DD;
        const float* V = g_v[s] + (size_t)b * MM * DD + h * DKK;
        int col0 = ct * 128;
        float (*a_sh)[132] = (float(*)[132])buf;
        float (*w_sh)[128] = (float(*)[128])(buf + 16896);

        #pragma unroll
        for (int i = 0; i < 4; i++) {
            int f = tid + i * 256;
            int r = f >> 3;
            int kq = (f & 7) * 4;
            float4 av = *(const float4*)(V + (size_t)r * DD + kq);
            a_sh[kq+0][r] = av.x; a_sh[kq+1][r] = av.y;
            a_sh[kq+2][r] = av.z; a_sh[kq+3][r] = av.w;
        }
        #pragma unroll
        for (int i = 0; i < 4; i++) {
            int idx = tid + i * 256;
            int kk = idx >> 5;
            int dq = (idx & 31) * 4;
            *(float4*)&w_sh[kk][dq] = *(const float4*)(Wo + (size_t)kk * DD + col0 + dq);
        }
        __syncthreads();

        int rg = tid & 15;
        int cg = tid >> 4;
        ull acc[4][8];
        #pragma unroll
        for (int p = 0; p < 4; p++)
            #pragma unroll
            for (int c = 0; c < 8; c++) acc[p][c] = 0ull;
        #pragma unroll
        for (int kk = 0; kk < 32; kk++) {
            ulonglong2 A0 = *(const ulonglong2*)&a_sh[kk][rg * 8];
            ulonglong2 A1 = *(const ulonglong2*)&a_sh[kk][rg * 8 + 4];
            float4 wa = *(const float4*)&w_sh[kk][cg * 8];
            float4 wb = *(const float4*)&w_sh[kk][cg * 8 + 4];
            ull wp[8] = { bcast2(wa.x), bcast2(wa.y), bcast2(wa.z), bcast2(wa.w),
                          bcast2(wb.x), bcast2(wb.y), bcast2(wb.z), bcast2(wb.w) };
            #pragma unroll
            for (int c = 0; c < 8; c++) {
                fma2(acc[0][c], A0.x, wp[c]);
                fma2(acc[1][c], A0.y, wp[c]);
                fma2(acc[2][c], A1.x, wp[c]);
                fma2(acc[3][c], A1.y, wp[c]);
            }
        }
        float* U = g_u[s] + ((size_t)(b * HH + h) * MM) * DD;
        #pragma unroll
        for (int p = 0; p < 4; p++) {
            float2 u0 = unpack2(acc[p][0]), u1 = unpack2(acc[p][1]);
            float2 u2 = unpack2(acc[p][2]), u3 = unpack2(acc[p][3]);
            float2 u4 = unpack2(acc[p][4]), u5 = unpack2(acc[p][5]);
            float2 u6 = unpack2(acc[p][6]), u7 = unpack2(acc[p][7]);
            int re = rg * 8 + 2 * p;
            float* d0 = U + (size_t)re * DD + col0 + cg * 8;
            float* d1 = d0 + DD;
            *(float4*)(d0)     = make_float4(u0.x, u1.x, u2.x, u3.x);
            *(float4*)(d0 + 4) = make_float4(u4.x, u5.x, u6.x, u7.x);
            *(float4*)(d1)     = make_float4(u0.y, u1.y, u2.y, u3.y);
            *(float4*)(d1 + 4) = make_float4(u4.y, u5.y, u6.y, u7.y);
        }
    } else if (blk < 272) {
        int id = blk - 256;
        int b = id & 7, s = id >> 3;
        const float* Wo = (s ? W_t : W_h) + 3 * 65536;
        float* vs = (float*)buf;
        int d = tid;
        const float* v = g_v[s] + (size_t)b * MM * DD;
        float sum = 0.f;
        for (int m = 0; m < MM; m++) sum += v[m * DD + d];
        vs[d] = sum;
        __syncthreads();
        float o = 0.f;
        for (int k = 0; k < DD; k++) o = fmaf(vs[k], Wo[(size_t)k * DD + d], o);
        g_usum[s][b * DD + d] = o;
    } else {
        int t = blk - 272;
        int h = t & 7, b = (t >> 3) & 7, s = t >> 6;
        float (*qs)[DKK + 1] = (float(*)[DKK + 1])buf;
        float (*ks)[DKK + 1] = (float(*)[DKK + 1])(buf + EE * (DKK + 1) * 4);
        const float* q = g_q[s] + (size_t)b * EE * DD + h * DKK;
        const float* k = g_k[s] + (size_t)b * MM * DD + h * DKK;
        for (int i = tid; i < EE * DKK; i += 256) { int r = i >> 5, c = i & 31; qs[r][c] = q[r * DD + c]; }
        for (int i = tid; i < MM * DKK; i += 256) { int r = i >> 5, c = i & 31; ks[r][c] = k[r * DD + c]; }
        __syncthreads();
        int j = tid >> 2;
        float* Srow = g_S[s] + ((size_t)(b * HH + h) * EE + j) * MM;
        const float scale = 0.17677669529663687f;
        for (int m = (tid & 3); m < MM; m += 4) {
            float acc = 0.f;
            #pragma unroll
            for (int c = 0; c < DKK; c++) acc = fmaf(qs[j][c], ks[m][c], acc);
            Srow[m] = acc * scale;
        }
    }
}

// ---------------- weights: wm[s][b][h][m][j] = softmax over entity mention list ----
__global__ __launch_bounds__(256) void k_w() {
    int i = blockIdx.x;
    int b = blockIdx.y;
    int s = blockIdx.z;
    int tid = threadIdx.x;
    int cnt = g_cnt[b * EE + i];
    if (cnt == 0) return;
    __shared__ int lst[MM];
    for (int t = tid; t < cnt; t += 256) lst[t] = g_list[(b * EE + i) * MM + t];
    __syncthreads();

    // 512 (h,j) tasks, 2 per thread
    #pragma unroll
    for (int task = tid; task < HH * EE; task += 256) {
        int h = task >> 6, j = task & 63;
        const float* Srow = g_S[s] + ((size_t)(b * HH + h) * EE + j) * MM;
        float m_ = -1e30f;
        for (int c = 0; c < cnt; c++) m_ = fmaxf(m_, Srow[lst[c]]);
        float se = 0.f;
        for (int c = 0; c < cnt; c++) se += __expf(Srow[lst[c]] - m_);
        float rinv = 1.0f / se;
        float* Wbase = g_wm[s] + (size_t)(b * HH + h) * MM * EE;
        for (int c = 0; c < cnt; c++) {
            int m0 = lst[c];
            Wbase[(size_t)m0 * EE + j] = __expf(Srow[m0] - m_) * rinv;
        }
    }
}

// ---------------- acc: out tile = sum_h sum_c wm * u + bo ; d split in halves -------
__global__ __launch_bounds__(256) void k_acc(const float* __restrict__ b_h,
                                             const float* __restrict__ b_t,
                                             float* __restrict__ out)
{
    int i = blockIdx.x;
    int b = blockIdx.y;
    int z = blockIdx.z;
    int s = z >> 1;
    int dh = (z & 1) * 128;   // d-half offset
    const float* bo = (s ? b_t : b_h) + 3 * 256 + dh;
    float* outS = out + (size_t)s * SETHALF + (size_t)b * NPAIR * DD + dh;
    int tid = threadIdx.x;
    int cnt = g_cnt[b * EE + i];

    if (cnt == 0) {
        const float* us = g_usum[s] + b * DD + dh;
        for (int idx = tid; idx < EE * 32; idx += 256) {
            int j = idx >> 5;
            int dq = idx & 31;
            float4 bo4 = *(const float4*)(bo + dq * 4);
            float4 u4 = *(const float4*)(us + dq * 4);
            float4 o = make_float4(bo4.x + u4.x * (1.0f/128.0f),
                                   bo4.y + u4.y * (1.0f/128.0f),
                                   bo4.z + u4.z * (1.0f/128.0f),
                                   bo4.w + u4.w * (1.0f/128.0f));
            int pair = (s == 0) ? (i * EE + j) : (j * EE + i);
            *(float4*)(outS + (size_t)pair * DD + dq * 4) = o;
        }
        return;
    }

    __shared__ float wsh[HH][WCH][EE];
    __shared__ int lst[MM];
    for (int t = tid; t < cnt; t += 256) lst[t] = g_list[(b * EE + i) * MM + t];
    __syncthreads();

    int dq = tid & 31;   // float4 index within 128-d half
    int jg = tid >> 5;   // 8 groups x 8 j
    ull acc[8][2];
    #pragma unroll
    for (int jj = 0; jj < 8; jj++) { acc[jj][0] = 0ull; acc[jj][1] = 0ull; }

    for (int base = 0; base < cnt; base += WCH) {
        int cEnd = min(WCH, cnt - base);
        int ce64 = cEnd << 6;
        #pragma unroll
        for (int h = 0; h < HH; h++) {
            const float* Wbase = g_wm[s] + (size_t)(b * HH + h) * MM * EE;
            for (int idx = tid; idx < ce64; idx += 256) {
                int c = idx >> 6, j = idx & 63;
                wsh[h][c][j] = Wbase[(size_t)lst[base + c] * EE + j];
            }
        }
        __syncthreads();
        #pragma unroll
        for (int h = 0; h < HH; h++) {
            for (int c = 0; c < cEnd; c++) {
                int m0 = lst[base + c];
                ulonglong2 U = *(const ulonglong2*)(g_u[s] +
                        ((size_t)(b * HH + h) * MM + m0) * DD + dh + dq * 4);
                const float* wrow = &wsh[h][c][jg * 8];
                float4 wa = *(const float4*)(wrow);
                float4 wb = *(const float4*)(wrow + 4);
                ull w0 = bcast2(wa.x), w1 = bcast2(wa.y), w2 = bcast2(wa.z), w3 = bcast2(wa.w);
                ull w4 = bcast2(wb.x), w5 = bcast2(wb.y), w6 = bcast2(wb.z), w7 = bcast2(wb.w);
                fma2(acc[0][0], w0, U.x); fma2(acc[0][1], w0, U.y);
                fma2(acc[1][0], w1, U.x); fma2(acc[1][1], w1, U.y);
                fma2(acc[2][0], w2, U.x); fma2(acc[2][1], w2, U.y);
                fma2(acc[3][0], w3, U.x); fma2(acc[3][1], w3, U.y);
                fma2(acc[4][0], w4, U.x); fma2(acc[4][1], w4, U.y);
                fma2(acc[5][0], w5, U.x); fma2(acc[5][1], w5, U.y);
                fma2(acc[6][0], w6, U.x); fma2(acc[6][1], w6, U.y);
                fma2(acc[7][0], w7, U.x); fma2(acc[7][1], w7, U.y);
            }
        }
        __syncthreads();
    }

    float4 bo4 = *(const float4*)(bo + dq * 4);
    #pragma unroll
    for (int jj = 0; jj < 8; jj++) {
        int j = jg * 8 + jj;
        int pair = (s == 0) ? (i * EE + j) : (j * EE + i);
        float2 p0 = unpack2(acc[jj][0]);
        float2 p1 = unpack2(acc[jj][1]);
        float4 o = make_float4(p0.x + bo4.x, p0.y + bo4.y, p1.x + bo4.z, p1.y + bo4.w);
        *(float4*)(outS + (size_t)pair * DD + dq * 4) = o;
    }
}

// ---------------- launch ----------------
extern "C" void kernel_launch(void* const* d_in, const int* in_sizes, int n_in,
                              void* d_out, int out_size) {
    const float* entities  = (const float*)d_in[0];
    const float* mentions  = (const float*)d_in[1];
    const float* sentences = (const float*)d_in[2];
    const int*   sent_ids  = (const int*)d_in[3];
    const int*   eid       = (const int*)d_in[4];
    const float* W_h       = (const float*)d_in[5];
    const float* b_h       = (const float*)d_in[6];
    const float* W_t       = (const float*)d_in[7];
    const float* b_t       = (const float*)d_in[8];
    float* out = (float*)d_out;

    k_prep<<<dim3(BB * MM + BB), 64>>>(sentences, sent_ids, eid);
    k_gemm_all<<<dim3(2, 10, BB), 256>>>(entities, mentions, W_h, b_h, W_t, b_t);
    k_mid<<<400, 256>>>(W_h, W_t);
    k_w<<<dim3(EE, BB, 2), 256>>>();
    k_acc<<<dim3(EE, BB, 4), 256>>>(b_h, b_t, out);
}

// round 4
// speedup vs baseline: 1.3435x; 1.3435x over previous
#include <cuda_runtime.h>

#define BB 8
#define EE 64
#define MM 128
#define DD 256
#define HH 8
#define DKK 32
#define NPAIR (EE*EE)
#define SETHALF (BB*NPAIR*DD)

typedef unsigned long long ull;

// ---- packed fp32x2 helpers ----
__device__ __forceinline__ void fma2(ull &d, ull a, ull b) {
    asm("fma.rn.f32x2 %0, %1, %2, %0;" : "+l"(d) : "l"(a), "l"(b));
}
__device__ __forceinline__ ull bcast2(float x) {
    ull d;
    asm("mov.b64 %0, {%1, %1};" : "=l"(d) : "r"(__float_as_uint(x)));
    return d;
}
__device__ __forceinline__ float2 unpack2(ull v) {
    float2 r;
    asm("mov.b64 {%0, %1}, %2;" : "=f"(r.x), "=f"(r.y) : "l"(v));
    return r;
}

// ---------------- scratch ----------------
__device__ float g_msr[BB*MM*DD];
__device__ float g_q[2][BB*EE*DD];
__device__ float g_k[2][BB*MM*DD];
__device__ float g_v[2][BB*MM*DD];
__device__ float g_u[2][BB*HH*MM*DD];
__device__ float g_S[2][BB*HH*MM*EE];    // TRANSPOSED: [s][b][h][m][j]  (j innermost!)
__device__ float g_usum[2][BB*DD];
__device__ int   g_cnt[BB*EE];
__device__ int   g_list[BB*EE*MM];

// ---------------- prep: gather msr + entity mention lists (fused) ----------------
__global__ void k_prep(const float* __restrict__ sentences,
                       const int* __restrict__ sent_ids,
                       const int* __restrict__ eid) {
    int blk = blockIdx.x;
    if (blk < BB * MM) {
        int b = blk >> 7, m = blk & 127;
        int sid = sent_ids[b*MM + m];
        const float4* src = (const float4*)(sentences + ((size_t)b*32 + sid)*DD);
        float4* dst = (float4*)(g_msr + ((size_t)b*MM + m)*DD);
        dst[threadIdx.x] = src[threadIdx.x];
    } else {
        int b = blk - BB * MM;
        int e = threadIdx.x;
        int cnt = 0;
        for (int m = 0; m < MM; m++)
            if (eid[b*MM + m] == e) g_list[(b*EE + e)*MM + cnt++] = m;
        g_cnt[b*EE + e] = cnt;
    }
}

// ---------------- six projections, 64x128 tiles, 8x4/thread, f32x2 ----------------
__global__ __launch_bounds__(256) void k_gemm_all(
    const float* __restrict__ entities, const float* __restrict__ mentions,
    const float* __restrict__ W_h, const float* __restrict__ b_h,
    const float* __restrict__ W_t, const float* __restrict__ b_t)
{
    __shared__ float a_sh[32][68];
    __shared__ float w_sh[32][128];
    int b = blockIdx.z;
    int y = blockIdx.y;
    int colTile = blockIdx.x;
    int job, rowTile;
    if (y < 2) { job = y; rowTile = 0; }
    else       { job = 2 + ((y - 2) >> 1); rowTile = (y - 2) & 1; }
    const float* A; const float* W; const float* bias; float* C; int rows;
    switch (job) {
      case 0:  A = entities; W = W_h;          bias = b_h;       C = g_q[0]; rows = EE; break;
      case 1:  A = entities; W = W_t;          bias = b_t;       C = g_q[1]; rows = EE; break;
      case 2:  A = g_msr;    W = W_h + 65536;  bias = b_h + 256; C = g_k[0]; rows = MM; break;
      case 3:  A = g_msr;    W = W_t + 65536;  bias = b_t + 256; C = g_k[1]; rows = MM; break;
      case 4:  A = mentions; W = W_h + 131072; bias = b_h + 512; C = g_v[0]; rows = MM; break;
      default: A = mentions; W = W_t + 131072; bias = b_t + 512; C = g_v[1]; rows = MM; break;
    }
    int row0 = rowTile * 64;
    int col0 = colTile * 128;
    const float* Ab = A + ((size_t)b * rows + row0) * DD;
    int tid = threadIdx.x;
    int rg = tid & 7;
    int cg = tid >> 3;
    ull acc[4][4];
    #pragma unroll
    for (int p = 0; p < 4; p++)
        #pragma unroll
        for (int c = 0; c < 4; c++) acc[p][c] = 0ull;

    for (int kc = 0; kc < 8; kc++) {
        int k0 = kc * 32;
        #pragma unroll
        for (int i = 0; i < 2; i++) {
            int f = tid * 2 + i;
            int r = f >> 3;
            int kq = (f & 7) * 4;
            float4 av = *(const float4*)(Ab + (size_t)r * DD + k0 + kq);
            a_sh[kq+0][r] = av.x; a_sh[kq+1][r] = av.y;
            a_sh[kq+2][r] = av.z; a_sh[kq+3][r] = av.w;
        }
        #pragma unroll
        for (int i = 0; i < 4; i++) {
            int idx = tid + i * 256;
            int kk = idx >> 5;
            int dq = (idx & 31) * 4;
            *(float4*)&w_sh[kk][dq] = *(const float4*)(W + (size_t)(k0 + kk) * DD + col0 + dq);
        }
        __syncthreads();
        #pragma unroll
        for (int kk = 0; kk < 32; kk++) {
            ulonglong2 A0 = *(const ulonglong2*)&a_sh[kk][rg * 8];
            ulonglong2 A1 = *(const ulonglong2*)&a_sh[kk][rg * 8 + 4];
            float4 wv = *(const float4*)&w_sh[kk][cg * 4];
            ull w0 = bcast2(wv.x), w1 = bcast2(wv.y), w2 = bcast2(wv.z), w3 = bcast2(wv.w);
            fma2(acc[0][0], A0.x, w0); fma2(acc[0][1], A0.x, w1);
            fma2(acc[0][2], A0.x, w2); fma2(acc[0][3], A0.x, w3);
            fma2(acc[1][0], A0.y, w0); fma2(acc[1][1], A0.y, w1);
            fma2(acc[1][2], A0.y, w2); fma2(acc[1][3], A0.y, w3);
            fma2(acc[2][0], A1.x, w0); fma2(acc[2][1], A1.x, w1);
            fma2(acc[2][2], A1.x, w2); fma2(acc[2][3], A1.x, w3);
            fma2(acc[3][0], A1.y, w0); fma2(acc[3][1], A1.y, w1);
            fma2(acc[3][2], A1.y, w2); fma2(acc[3][3], A1.y, w3);
        }
        __syncthreads();
    }
    float4 bi = *(const float4*)(bias + col0 + cg * 4);
    #pragma unroll
    for (int p = 0; p < 4; p++) {
        float2 c0 = unpack2(acc[p][0]), c1 = unpack2(acc[p][1]);
        float2 c2 = unpack2(acc[p][2]), c3 = unpack2(acc[p][3]);
        int re = row0 + rg * 8 + 2 * p;
        float4 oe = make_float4(c0.x + bi.x, c1.x + bi.y, c2.x + bi.z, c3.x + bi.w);
        float4 oo = make_float4(c0.y + bi.x, c1.y + bi.y, c2.y + bi.z, c3.y + bi.w);
        *(float4*)(C + ((size_t)b * rows + re)     * DD + col0 + cg * 4) = oe;
        *(float4*)(C + ((size_t)b * rows + re + 1) * DD + col0 + cg * 4) = oo;
    }
}

// ---------------- mid: uproj (256 blks) + usum (16 blks) + scores (128 blks) --------
__global__ __launch_bounds__(256) void k_mid(const float* __restrict__ W_h,
                                             const float* __restrict__ W_t)
{
    __shared__ __align__(16) char buf[33792];
    int blk = blockIdx.x;
    int tid = threadIdx.x;

    if (blk < 256) {
        int ct = blk & 1;
        int g = blk >> 1;
        int s = g >> 6, b = (g >> 3) & 7, h = g & 7;
        const float* Wo = (s ? W_t : W_h) + 3 * 65536 + h * DKK * DD;
        const float* V = g_v[s] + (size_t)b * MM * DD + h * DKK;
        int col0 = ct * 128;
        float (*a_sh)[132] = (float(*)[132])buf;
        float (*w_sh)[128] = (float(*)[128])(buf + 16896);

        #pragma unroll
        for (int i = 0; i < 4; i++) {
            int f = tid + i * 256;
            int r = f >> 3;
            int kq = (f & 7) * 4;
            float4 av = *(const float4*)(V + (size_t)r * DD + kq);
            a_sh[kq+0][r] = av.x; a_sh[kq+1][r] = av.y;
            a_sh[kq+2][r] = av.z; a_sh[kq+3][r] = av.w;
        }
        #pragma unroll
        for (int i = 0; i < 4; i++) {
            int idx = tid + i * 256;
            int kk = idx >> 5;
            int dq = (idx & 31) * 4;
            *(float4*)&w_sh[kk][dq] = *(const float4*)(Wo + (size_t)kk * DD + col0 + dq);
        }
        __syncthreads();

        int rg = tid & 15;
        int cg = tid >> 4;
        ull acc[4][8];
        #pragma unroll
        for (int p = 0; p < 4; p++)
            #pragma unroll
            for (int c = 0; c < 8; c++) acc[p][c] = 0ull;
        #pragma unroll
        for (int kk = 0; kk < 32; kk++) {
            ulonglong2 A0 = *(const ulonglong2*)&a_sh[kk][rg * 8];
            ulonglong2 A1 = *(const ulonglong2*)&a_sh[kk][rg * 8 + 4];
            float4 wa = *(const float4*)&w_sh[kk][cg * 8];
            float4 wb = *(const float4*)&w_sh[kk][cg * 8 + 4];
            ull wp[8] = { bcast2(wa.x), bcast2(wa.y), bcast2(wa.z), bcast2(wa.w),
                          bcast2(wb.x), bcast2(wb.y), bcast2(wb.z), bcast2(wb.w) };
            #pragma unroll
            for (int c = 0; c < 8; c++) {
                fma2(acc[0][c], A0.x, wp[c]);
                fma2(acc[1][c], A0.y, wp[c]);
                fma2(acc[2][c], A1.x, wp[c]);
                fma2(acc[3][c], A1.y, wp[c]);
            }
        }
        float* U = g_u[s] + ((size_t)(b * HH + h) * MM) * DD;
        #pragma unroll
        for (int p = 0; p < 4; p++) {
            float2 u0 = unpack2(acc[p][0]), u1 = unpack2(acc[p][1]);
            float2 u2 = unpack2(acc[p][2]), u3 = unpack2(acc[p][3]);
            float2 u4 = unpack2(acc[p][4]), u5 = unpack2(acc[p][5]);
            float2 u6 = unpack2(acc[p][6]), u7 = unpack2(acc[p][7]);
            int re = rg * 8 + 2 * p;
            float* d0 = U + (size_t)re * DD + col0 + cg * 8;
            float* d1 = d0 + DD;
            *(float4*)(d0)     = make_float4(u0.x, u1.x, u2.x, u3.x);
            *(float4*)(d0 + 4) = make_float4(u4.x, u5.x, u6.x, u7.x);
            *(float4*)(d1)     = make_float4(u0.y, u1.y, u2.y, u3.y);
            *(float4*)(d1 + 4) = make_float4(u4.y, u5.y, u6.y, u7.y);
        }
    } else if (blk < 272) {
        int id = blk - 256;
        int b = id & 7, s = id >> 3;
        const float* Wo = (s ? W_t : W_h) + 3 * 65536;
        float* vs = (float*)buf;
        int d = tid;
        const float* v = g_v[s] + (size_t)b * MM * DD;
        float sum = 0.f;
        for (int m = 0; m < MM; m++) sum += v[m * DD + d];
        vs[d] = sum;
        __syncthreads();
        float o = 0.f;
        for (int k = 0; k < DD; k++) o = fmaf(vs[k], Wo[(size_t)k * DD + d], o);
        g_usum[s][b * DD + d] = o;
    } else {
        // scores, TRANSPOSED output: S[s][b][h][m][j]
        int t = blk - 272;
        int h = t & 7, b = (t >> 3) & 7, s = t >> 6;
        float (*qs)[DKK + 1] = (float(*)[DKK + 1])buf;
        float (*ks)[DKK + 1] = (float(*)[DKK + 1])(buf + EE * (DKK + 1) * 4);
        const float* q = g_q[s] + (size_t)b * EE * DD + h * DKK;
        const float* k = g_k[s] + (size_t)b * MM * DD + h * DKK;
        for (int i = tid; i < EE * DKK; i += 256) { int r = i >> 5, c = i & 31; qs[r][c] = q[r * DD + c]; }
        for (int i = tid; i < MM * DKK; i += 256) { int r = i >> 5, c = i & 31; ks[r][c] = k[r * DD + c]; }
        __syncthreads();
        int j = tid & 63;
        int m0 = tid >> 6;
        float* Sbase = g_S[s] + (size_t)(b * HH + h) * MM * EE;
        const float scale = 0.17677669529663687f;
        for (int m = m0; m < MM; m += 4) {
            float acc = 0.f;
            #pragma unroll
            for (int c = 0; c < DKK; c++) acc = fmaf(qs[j][c], ks[m][c], acc);
            Sbase[(size_t)m * EE + j] = acc * scale;   // coalesced in j
        }
    }
}

// ---------------- fused output: stats + weights + accumulate + store ---------------
// grid (EE, BB, 2), 256 threads, full 64j x 256d (64KB) per block.
// All gmem reads coalesced (S is [h][m][j]); accumulate entirely from smem.
__global__ __launch_bounds__(256) void k_out2(const float* __restrict__ b_h,
                                              const float* __restrict__ b_t,
                                              float* __restrict__ out)
{
    int i = blockIdx.x;
    int b = blockIdx.y;
    int s = blockIdx.z;
    const float* bo = (s ? b_t : b_h) + 3 * 256;
    float* outS = out + (size_t)s * SETHALF + (size_t)b * NPAIR * DD;
    int tid = threadIdx.x;
    int cnt = g_cnt[b * EE + i];

    if (cnt == 0) {
        const float* us = g_usum[s] + b * DD;
        for (int idx = tid; idx < EE * 64; idx += 256) {
            int j = idx >> 6;
            int q = idx & 63;
            float4 bo4 = *(const float4*)(bo + q * 4);
            float4 u4 = *(const float4*)(us + q * 4);
            float4 o = make_float4(bo4.x + u4.x * (1.0f/128.0f),
                                   bo4.y + u4.y * (1.0f/128.0f),
                                   bo4.z + u4.z * (1.0f/128.0f),
                                   bo4.w + u4.w * (1.0f/128.0f));
            int pair = (s == 0) ? (i * EE + j) : (j * EE + i);
            *(float4*)(outS + (size_t)pair * DD + q * 4) = o;
        }
        return;
    }

    __shared__ int lst[MM];
    __shared__ float mx[HH][EE];
    __shared__ float rs[HH][EE];
    __shared__ float wsh[HH][4][EE];     // weights, one chunk (<=4 mentions)
    __shared__ float sU[HH][4][DD];      // staged u rows, one chunk

    for (int t = tid; t < cnt; t += 256) lst[t] = g_list[(b * EE + i) * MM + t];
    __syncthreads();

    const float* Sb = g_S[s] + (size_t)(b * HH) * MM * EE;

    // stats: 512 (h,j) tasks; all loads are coalesced 256B rows (lanes = consecutive j)
    #pragma unroll
    for (int task = tid; task < HH * EE; task += 256) {
        int h = task >> 6, j = task & 63;
        const float* Sh = Sb + (size_t)h * MM * EE + j;
        float m_ = -1e30f;
        for (int c = 0; c < cnt; c++) m_ = fmaxf(m_, Sh[(size_t)lst[c] * EE]);
        float se = 0.f;
        for (int c = 0; c < cnt; c++) se += __expf(Sh[(size_t)lst[c] * EE] - m_);
        mx[h][j] = m_;
        rs[h][j] = 1.0f / se;
    }
    __syncthreads();

    int dq = tid & 31;    // d = dq*8 .. dq*8+7
    int jg = tid >> 5;    // j = jg*8 .. jg*8+7
    ull acc[8][4];
    #pragma unroll
    for (int jj = 0; jj < 8; jj++)
        #pragma unroll
        for (int p = 0; p < 4; p++) acc[jj][p] = 0ull;

    for (int base = 0; base < cnt; base += 4) {
        int ce = min(4, cnt - base);
        // weights: coalesced S row reads + exp
        for (int t = tid; t < 2048; t += 256) {
            int h = t >> 8, c = (t >> 6) & 3, j = t & 63;
            if (c < ce) {
                int m0 = lst[base + c];
                float sv = Sb[((size_t)h * MM + m0) * EE + j];
                wsh[h][c][j] = __expf(sv - mx[h][j]) * rs[h][j];
            }
        }
        // stage u rows: fully parallel float4 loads (high MLP)
        for (int t = tid; t < 2048; t += 256) {
            int h = t >> 8, c = (t >> 6) & 3, q = t & 63;
            if (c < ce) {
                int m0 = lst[base + c];
                *(float4*)&sU[h][c][q * 4] =
                    *(const float4*)(g_u[s] + ((size_t)(b * HH + h) * MM + m0) * DD + q * 4);
            }
        }
        __syncthreads();
        for (int c = 0; c < ce; c++) {
            #pragma unroll
            for (int h = 0; h < HH; h++) {
                ulonglong2 Ua = *(const ulonglong2*)&sU[h][c][dq * 8];
                ulonglong2 Ub = *(const ulonglong2*)&sU[h][c][dq * 8 + 4];
                float4 wa = *(const float4*)&wsh[h][c][jg * 8];      // broadcast
                float4 wb = *(const float4*)&wsh[h][c][jg * 8 + 4];  // broadcast
                ull w0 = bcast2(wa.x), w1 = bcast2(wa.y), w2 = bcast2(wa.z), w3 = bcast2(wa.w);
                ull w4 = bcast2(wb.x), w5 = bcast2(wb.y), w6 = bcast2(wb.z), w7 = bcast2(wb.w);
                fma2(acc[0][0], w0, Ua.x); fma2(acc[0][1], w0, Ua.y);
                fma2(acc[0][2], w0, Ub.x); fma2(acc[0][3], w0, Ub.y);
                fma2(acc[1][0], w1, Ua.x); fma2(acc[1][1], w1, Ua.y);
                fma2(acc[1][2], w1, Ub.x); fma2(acc[1][3], w1, Ub.y);
                fma2(acc[2][0], w2, Ua.x); fma2(acc[2][1], w2, Ua.y);
                fma2(acc[2][2], w2, Ub.x); fma2(acc[2][3], w2, Ub.y);
                fma2(acc[3][0], w3, Ua.x); fma2(acc[3][1], w3, Ua.y);
                fma2(acc[3][2], w3, Ub.x); fma2(acc[3][3], w3, Ub.y);
                fma2(acc[4][0], w4, Ua.x); fma2(acc[4][1], w4, Ua.y);
                fma2(acc[4][2], w4, Ub.x); fma2(acc[4][3], w4, Ub.y);
                fma2(acc[5][0], w5, Ua.x); fma2(acc[5][1], w5, Ua.y);
                fma2(acc[5][2], w5, Ub.x); fma2(acc[5][3], w5, Ub.y);
                fma2(acc[6][0], w6, Ua.x); fma2(acc[6][1], w6, Ua.y);
                fma2(acc[6][2], w6, Ub.x); fma2(acc[6][3], w6, Ub.y);
                fma2(acc[7][0], w7, Ua.x); fma2(acc[7][1], w7, Ua.y);
                fma2(acc[7][2], w7, Ub.x); fma2(acc[7][3], w7, Ub.y);
            }
        }
        __syncthreads();
    }

    float4 bo0 = *(const float4*)(bo + dq * 8);
    float4 bo1 = *(const float4*)(bo + dq * 8 + 4);
    #pragma unroll
    for (int jj = 0; jj < 8; jj++) {
        int j = jg * 8 + jj;
        int pair = (s == 0) ? (i * EE + j) : (j * EE + i);
        float2 p0 = unpack2(acc[jj][0]);
        float2 p1 = unpack2(acc[jj][1]);
        float2 p2 = unpack2(acc[jj][2]);
        float2 p3 = unpack2(acc[jj][3]);
        float* dst = outS + (size_t)pair * DD + dq * 8;
        *(float4*)(dst)     = make_float4(p0.x + bo0.x, p0.y + bo0.y, p1.x + bo0.z, p1.y + bo0.w);
        *(float4*)(dst + 4) = make_float4(p2.x + bo1.x, p2.y + bo1.y, p3.x + bo1.z, p3.y + bo1.w);
    }
}

// ---------------- launch ----------------
extern "C" void kernel_launch(void* const* d_in, const int* in_sizes, int n_in,
                              void* d_out, int out_size) {
    const float* entities  = (const float*)d_in[0];
    const float* mentions  = (const float*)d_in[1];
    const float* sentences = (const float*)d_in[2];
    const int*   sent_ids  = (const int*)d_in[3];
    const int*   eid       = (const int*)d_in[4];
    const float* W_h       = (const float*)d_in[5];
    const float* b_h       = (const float*)d_in[6];
    const float* W_t       = (const float*)d_in[7];
    const float* b_t       = (const float*)d_in[8];
    float* out = (float*)d_out;

    k_prep<<<dim3(BB * MM + BB), 64>>>(sentences, sent_ids, eid);
    k_gemm_all<<<dim3(2, 10, BB), 256>>>(entities, mentions, W_h, b_h, W_t, b_t);
    k_mid<<<400, 256>>>(W_h, W_t);
    k_out2<<<dim3(EE, BB, 2), 256>>>(b_h, b_t, out);
}

// round 5
// speedup vs baseline: 1.4019x; 1.0435x over previous
#include <cuda_runtime.h>

#define BB 8
#define EE 64
#define MM 128
#define DD 256
#define HH 8
#define DKK 32
#define NPAIR (EE*EE)
#define SETHALF (BB*NPAIR*DD)

typedef unsigned long long ull;

// ---- packed fp32x2 helpers ----
__device__ __forceinline__ void fma2(ull &d, ull a, ull b) {
    asm("fma.rn.f32x2 %0, %1, %2, %0;" : "+l"(d) : "l"(a), "l"(b));
}
__device__ __forceinline__ ull bcast2(float x) {
    ull d;
    asm("mov.b64 %0, {%1, %1};" : "=l"(d) : "r"(__float_as_uint(x)));
    return d;
}
__device__ __forceinline__ float2 unpack2(ull v) {
    float2 r;
    asm("mov.b64 {%0, %1}, %2;" : "=f"(r.x), "=f"(r.y) : "l"(v));
    return r;
}

// ---------------- scratch ----------------
__device__ float g_msr[BB*MM*DD];
__device__ float g_q[2][BB*EE*DD];
__device__ float g_k[2][BB*MM*DD];
__device__ float g_v[2][BB*MM*DD];
__device__ float g_u[2][BB*HH*MM*DD];
__device__ float g_S[2][BB*HH*MM*EE];    // TRANSPOSED: [s][b][h][m][j]  (j innermost)
__device__ float g_usum[2][BB*DD];
__device__ int   g_cnt[BB*EE];
__device__ int   g_list[BB*EE*MM];

// ---------------- prep: gather msr + entity mention lists (fused) ----------------
__global__ void k_prep(const float* __restrict__ sentences,
                       const int* __restrict__ sent_ids,
                       const int* __restrict__ eid) {
    int blk = blockIdx.x;
    if (blk < BB * MM) {
        int b = blk >> 7, m = blk & 127;
        int sid = sent_ids[b*MM + m];
        const float4* src = (const float4*)(sentences + ((size_t)b*32 + sid)*DD);
        float4* dst = (float4*)(g_msr + ((size_t)b*MM + m)*DD);
        dst[threadIdx.x] = src[threadIdx.x];
    } else {
        int b = blk - BB * MM;
        int e = threadIdx.x;
        int cnt = 0;
        for (int m = 0; m < MM; m++)
            if (eid[b*MM + m] == e) g_list[(b*EE + e)*MM + cnt++] = m;
        g_cnt[b*EE + e] = cnt;
    }
}

// ---------------- six projections, 64x128 tiles, 8x4/thread, f32x2 ----------------
__global__ __launch_bounds__(256) void k_gemm_all(
    const float* __restrict__ entities, const float* __restrict__ mentions,
    const float* __restrict__ W_h, const float* __restrict__ b_h,
    const float* __restrict__ W_t, const float* __restrict__ b_t)
{
    __shared__ float a_sh[32][68];
    __shared__ float w_sh[32][128];
    int b = blockIdx.z;
    int y = blockIdx.y;
    int colTile = blockIdx.x;
    int job, rowTile;
    if (y < 2) { job = y; rowTile = 0; }
    else       { job = 2 + ((y - 2) >> 1); rowTile = (y - 2) & 1; }
    const float* A; const float* W; const float* bias; float* C; int rows;
    switch (job) {
      case 0:  A = entities; W = W_h;          bias = b_h;       C = g_q[0]; rows = EE; break;
      case 1:  A = entities; W = W_t;          bias = b_t;       C = g_q[1]; rows = EE; break;
      case 2:  A = g_msr;    W = W_h + 65536;  bias = b_h + 256; C = g_k[0]; rows = MM; break;
      case 3:  A = g_msr;    W = W_t + 65536;  bias = b_t + 256; C = g_k[1]; rows = MM; break;
      case 4:  A = mentions; W = W_h + 131072; bias = b_h + 512; C = g_v[0]; rows = MM; break;
      default: A = mentions; W = W_t + 131072; bias = b_t + 512; C = g_v[1]; rows = MM; break;
    }
    int row0 = rowTile * 64;
    int col0 = colTile * 128;
    const float* Ab = A + ((size_t)b * rows + row0) * DD;
    int tid = threadIdx.x;
    int rg = tid & 7;
    int cg = tid >> 3;
    ull acc[4][4];
    #pragma unroll
    for (int p = 0; p < 4; p++)
        #pragma unroll
        for (int c = 0; c < 4; c++) acc[p][c] = 0ull;

    for (int kc = 0; kc < 8; kc++) {
        int k0 = kc * 32;
        #pragma unroll
        for (int i = 0; i < 2; i++) {
            int f = tid * 2 + i;
            int r = f >> 3;
            int kq = (f & 7) * 4;
            float4 av = *(const float4*)(Ab + (size_t)r * DD + k0 + kq);
            a_sh[kq+0][r] = av.x; a_sh[kq+1][r] = av.y;
            a_sh[kq+2][r] = av.z; a_sh[kq+3][r] = av.w;
        }
        #pragma unroll
        for (int i = 0; i < 4; i++) {
            int idx = tid + i * 256;
            int kk = idx >> 5;
            int dq = (idx & 31) * 4;
            *(float4*)&w_sh[kk][dq] = *(const float4*)(W + (size_t)(k0 + kk) * DD + col0 + dq);
        }
        __syncthreads();
        #pragma unroll
        for (int kk = 0; kk < 32; kk++) {
            ulonglong2 A0 = *(const ulonglong2*)&a_sh[kk][rg * 8];
            ulonglong2 A1 = *(const ulonglong2*)&a_sh[kk][rg * 8 + 4];
            float4 wv = *(const float4*)&w_sh[kk][cg * 4];
            ull w0 = bcast2(wv.x), w1 = bcast2(wv.y), w2 = bcast2(wv.z), w3 = bcast2(wv.w);
            fma2(acc[0][0], A0.x, w0); fma2(acc[0][1], A0.x, w1);
            fma2(acc[0][2], A0.x, w2); fma2(acc[0][3], A0.x, w3);
            fma2(acc[1][0], A0.y, w0); fma2(acc[1][1], A0.y, w1);
            fma2(acc[1][2], A0.y, w2); fma2(acc[1][3], A0.y, w3);
            fma2(acc[2][0], A1.x, w0); fma2(acc[2][1], A1.x, w1);
            fma2(acc[2][2], A1.x, w2); fma2(acc[2][3], A1.x, w3);
            fma2(acc[3][0], A1.y, w0); fma2(acc[3][1], A1.y, w1);
            fma2(acc[3][2], A1.y, w2); fma2(acc[3][3], A1.y, w3);
        }
        __syncthreads();
    }
    float4 bi = *(const float4*)(bias + col0 + cg * 4);
    #pragma unroll
    for (int p = 0; p < 4; p++) {
        float2 c0 = unpack2(acc[p][0]), c1 = unpack2(acc[p][1]);
        float2 c2 = unpack2(acc[p][2]), c3 = unpack2(acc[p][3]);
        int re = row0 + rg * 8 + 2 * p;
        float4 oe = make_float4(c0.x + bi.x, c1.x + bi.y, c2.x + bi.z, c3.x + bi.w);
        float4 oo = make_float4(c0.y + bi.x, c1.y + bi.y, c2.y + bi.z, c3.y + bi.w);
        *(float4*)(C + ((size_t)b * rows + re)     * DD + col0 + cg * 4) = oe;
        *(float4*)(C + ((size_t)b * rows + re + 1) * DD + col0 + cg * 4) = oo;
    }
}

// ---------------- mid: uproj (256 blks) + usum (16 blks) + scores (128 blks) --------
__global__ __launch_bounds__(256) void k_mid(const float* __restrict__ W_h,
                                             const float* __restrict__ W_t)
{
    __shared__ __align__(16) char buf[33792];
    int blk = blockIdx.x;
    int tid = threadIdx.x;

    if (blk < 256) {
        int ct = blk & 1;
        int g = blk >> 1;
        int s = g >> 6, b = (g >> 3) & 7, h = g & 7;
        const float* Wo = (s ? W_t : W_h) + 3 * 65536 + h * DKK * DD;
        const float* V = g_v[s] + (size_t)b * MM * DD + h * DKK;
        int col0 = ct * 128;
        float (*a_sh)[132] = (float(*)[132])buf;
        float (*w_sh)[128] = (float(*)[128])(buf + 16896);

        #pragma unroll
        for (int i = 0; i < 4; i++) {
            int f = tid + i * 256;
            int r = f >> 3;
            int kq = (f & 7) * 4;
            float4 av = *(const float4*)(V + (size_t)r * DD + kq);
            a_sh[kq+0][r] = av.x; a_sh[kq+1][r] = av.y;
            a_sh[kq+2][r] = av.z; a_sh[kq+3][r] = av.w;
        }
        #pragma unroll
        for (int i = 0; i < 4; i++) {
            int idx = tid + i * 256;
            int kk = idx >> 5;
            int dq = (idx & 31) * 4;
            *(float4*)&w_sh[kk][dq] = *(const float4*)(Wo + (size_t)kk * DD + col0 + dq);
        }
        __syncthreads();

        int rg = tid & 15;
        int cg = tid >> 4;
        ull acc[4][8];
        #pragma unroll
        for (int p = 0; p < 4; p++)
            #pragma unroll
            for (int c = 0; c < 8; c++) acc[p][c] = 0ull;
        #pragma unroll
        for (int kk = 0; kk < 32; kk++) {
            ulonglong2 A0 = *(const ulonglong2*)&a_sh[kk][rg * 8];
            ulonglong2 A1 = *(const ulonglong2*)&a_sh[kk][rg * 8 + 4];
            float4 wa = *(const float4*)&w_sh[kk][cg * 8];
            float4 wb = *(const float4*)&w_sh[kk][cg * 8 + 4];
            ull wp[8] = { bcast2(wa.x), bcast2(wa.y), bcast2(wa.z), bcast2(wa.w),
                          bcast2(wb.x), bcast2(wb.y), bcast2(wb.z), bcast2(wb.w) };
            #pragma unroll
            for (int c = 0; c < 8; c++) {
                fma2(acc[0][c], A0.x, wp[c]);
                fma2(acc[1][c], A0.y, wp[c]);
                fma2(acc[2][c], A1.x, wp[c]);
                fma2(acc[3][c], A1.y, wp[c]);
            }
        }
        float* U = g_u[s] + ((size_t)(b * HH + h) * MM) * DD;
        #pragma unroll
        for (int p = 0; p < 4; p++) {
            float2 u0 = unpack2(acc[p][0]), u1 = unpack2(acc[p][1]);
            float2 u2 = unpack2(acc[p][2]), u3 = unpack2(acc[p][3]);
            float2 u4 = unpack2(acc[p][4]), u5 = unpack2(acc[p][5]);
            float2 u6 = unpack2(acc[p][6]), u7 = unpack2(acc[p][7]);
            int re = rg * 8 + 2 * p;
            float* d0 = U + (size_t)re * DD + col0 + cg * 8;
            float* d1 = d0 + DD;
            *(float4*)(d0)     = make_float4(u0.x, u1.x, u2.x, u3.x);
            *(float4*)(d0 + 4) = make_float4(u4.x, u5.x, u6.x, u7.x);
            *(float4*)(d1)     = make_float4(u0.y, u1.y, u2.y, u3.y);
            *(float4*)(d1 + 4) = make_float4(u4.y, u5.y, u6.y, u7.y);
        }
    } else if (blk < 272) {
        int id = blk - 256;
        int b = id & 7, s = id >> 3;
        const float* Wo = (s ? W_t : W_h) + 3 * 65536;
        float* vs = (float*)buf;
        int d = tid;
        const float* v = g_v[s] + (size_t)b * MM * DD;
        float sum = 0.f;
        for (int m = 0; m < MM; m++) sum += v[m * DD + d];
        vs[d] = sum;
        __syncthreads();
        float o = 0.f;
        for (int k = 0; k < DD; k++) o = fmaf(vs[k], Wo[(size_t)k * DD + d], o);
        g_usum[s][b * DD + d] = o;
    } else {
        // scores, TRANSPOSED output: S[s][b][h][m][j]
        int t = blk - 272;
        int h = t & 7, b = (t >> 3) & 7, s = t >> 6;
        float (*qs)[DKK + 1] = (float(*)[DKK + 1])buf;
        float (*ks)[DKK + 1] = (float(*)[DKK + 1])(buf + EE * (DKK + 1) * 4);
        const float* q = g_q[s] + (size_t)b * EE * DD + h * DKK;
        const float* k = g_k[s] + (size_t)b * MM * DD + h * DKK;
        for (int i = tid; i < EE * DKK; i += 256) { int r = i >> 5, c = i & 31; qs[r][c] = q[r * DD + c]; }
        for (int i = tid; i < MM * DKK; i += 256) { int r = i >> 5, c = i & 31; ks[r][c] = k[r * DD + c]; }
        __syncthreads();
        int j = tid & 63;
        int m0 = tid >> 6;
        float* Sbase = g_S[s] + (size_t)(b * HH + h) * MM * EE;
        const float scale = 0.17677669529663687f;
        for (int m = m0; m < MM; m += 4) {
            float acc = 0.f;
            #pragma unroll
            for (int c = 0; c < DKK; c++) acc = fmaf(qs[j][c], ks[m][c], acc);
            Sbase[(size_t)m * EE + j] = acc * scale;   // coalesced in j
        }
    }
}

// ---------------- fused output, j-split: grid (EE, BB, 4); z = s*2 + jhalf ----------
// Per block: 32 j x 256 d. Thread tile 8j x 4d (acc 16 ull). No u staging (L1-hot LDG).
__global__ __launch_bounds__(256, 3) void k_out2(const float* __restrict__ b_h,
                                                 const float* __restrict__ b_t,
                                                 float* __restrict__ out)
{
    int i = blockIdx.x;
    int b = blockIdx.y;
    int z = blockIdx.z;
    int s = z >> 1;
    int j0 = (z & 1) * 32;
    const float* bo = (s ? b_t : b_h) + 3 * 256;
    float* outS = out + (size_t)s * SETHALF + (size_t)b * NPAIR * DD;
    int tid = threadIdx.x;
    int cnt = g_cnt[b * EE + i];

    if (cnt == 0) {
        const float* us = g_usum[s] + b * DD;
        for (int idx = tid; idx < 32 * 64; idx += 256) {
            int j = j0 + (idx >> 6);
            int q = idx & 63;
            float4 bo4 = *(const float4*)(bo + q * 4);
            float4 u4 = *(const float4*)(us + q * 4);
            float4 o = make_float4(bo4.x + u4.x * (1.0f/128.0f),
                                   bo4.y + u4.y * (1.0f/128.0f),
                                   bo4.z + u4.z * (1.0f/128.0f),
                                   bo4.w + u4.w * (1.0f/128.0f));
            int pair = (s == 0) ? (i * EE + j) : (j * EE + i);
            *(float4*)(outS + (size_t)pair * DD + q * 4) = o;
        }
        return;
    }

    __shared__ int lst[MM];
    __shared__ float mx[HH][32];
    __shared__ float rs[HH][32];
    __shared__ float wsh[HH][4][32];

    for (int t = tid; t < cnt; t += 256) lst[t] = g_list[(b * EE + i) * MM + t];
    __syncthreads();

    const float* Sb = g_S[s] + (size_t)(b * HH) * MM * EE;

    // stats: exactly one (h, j) task per thread; coalesced 128B S-row reads
    {
        int h = tid >> 5;
        int jl = tid & 31;
        const float* Sh = Sb + (size_t)h * MM * EE + j0 + jl;
        float m_ = -1e30f;
        for (int c = 0; c < cnt; c++) m_ = fmaxf(m_, Sh[(size_t)lst[c] * EE]);
        float se = 0.f;
        for (int c = 0; c < cnt; c++) se += __expf(Sh[(size_t)lst[c] * EE] - m_);
        mx[h][jl] = m_;
        rs[h][jl] = 1.0f / se;
    }
    __syncthreads();

    int dq = tid & 63;    // d = dq*4 .. dq*4+3
    int jg = tid >> 6;    // j = j0 + jg*8 .. +7
    ull acc[8][2];
    #pragma unroll
    for (int jj = 0; jj < 8; jj++) { acc[jj][0] = 0ull; acc[jj][1] = 0ull; }

    const float* Ub = g_u[s] + (size_t)(b * HH) * MM * DD + dq * 4;

    for (int base = 0; base < cnt; base += 4) {
        int ce = min(4, cnt - base);
        // weights: 8h x 4c x 32j = 1024 entries, 4/thread, coalesced in j
        for (int t = tid; t < HH * 4 * 32; t += 256) {
            int h = t >> 7, c = (t >> 5) & 3, jl = t & 31;
            if (c < ce) {
                int m0 = lst[base + c];
                float sv = Sb[((size_t)h * MM + m0) * EE + j0 + jl];
                wsh[h][c][jl] = __expf(sv - mx[h][jl]) * rs[h][jl];
            }
        }
        __syncthreads();
        for (int c = 0; c < ce; c++) {
            int m0 = lst[base + c];
            #pragma unroll
            for (int h = 0; h < HH; h++) {
                ulonglong2 U = *(const ulonglong2*)(Ub + ((size_t)h * MM + m0) * DD);
                const float* wr = &wsh[h][c][jg * 8];
                float4 wa = *(const float4*)(wr);       // warp-broadcast LDS
                float4 wb = *(const float4*)(wr + 4);
                ull w0 = bcast2(wa.x), w1 = bcast2(wa.y), w2 = bcast2(wa.z), w3 = bcast2(wa.w);
                ull w4 = bcast2(wb.x), w5 = bcast2(wb.y), w6 = bcast2(wb.z), w7 = bcast2(wb.w);
                fma2(acc[0][0], w0, U.x); fma2(acc[0][1], w0, U.y);
                fma2(acc[1][0], w1, U.x); fma2(acc[1][1], w1, U.y);
                fma2(acc[2][0], w2, U.x); fma2(acc[2][1], w2, U.y);
                fma2(acc[3][0], w3, U.x); fma2(acc[3][1], w3, U.y);
                fma2(acc[4][0], w4, U.x); fma2(acc[4][1], w4, U.y);
                fma2(acc[5][0], w5, U.x); fma2(acc[5][1], w5, U.y);
                fma2(acc[6][0], w6, U.x); fma2(acc[6][1], w6, U.y);
                fma2(acc[7][0], w7, U.x); fma2(acc[7][1], w7, U.y);
            }
        }
        __syncthreads();
    }

    float4 bo4 = *(const float4*)(bo + dq * 4);
    #pragma unroll
    for (int jj = 0; jj < 8; jj++) {
        int j = j0 + jg * 8 + jj;
        int pair = (s == 0) ? (i * EE + j) : (j * EE + i);
        float2 p0 = unpack2(acc[jj][0]);
        float2 p1 = unpack2(acc[jj][1]);
        float4 o = make_float4(p0.x + bo4.x, p0.y + bo4.y, p1.x + bo4.z, p1.y + bo4.w);
        *(float4*)(outS + (size_t)pair * DD + dq * 4) = o;
    }
}

// ---------------- launch ----------------
extern "C" void kernel_launch(void* const* d_in, const int* in_sizes, int n_in,
                              void* d_out, int out_size) {
    const float* entities  = (const float*)d_in[0];
    const float* mentions  = (const float*)d_in[1];
    const float* sentences = (const float*)d_in[2];
    const int*   sent_ids  = (const int*)d_in[3];
    const int*   eid       = (const int*)d_in[4];
    const float* W_h       = (const float*)d_in[5];
    const float* b_h       = (const float*)d_in[6];
    const float* W_t       = (const float*)d_in[7];
    const float* b_t       = (const float*)d_in[8];
    float* out = (float*)d_out;

    k_prep<<<dim3(BB * MM + BB), 64>>>(sentences, sent_ids, eid);
    k_gemm_all<<<dim3(2, 10, BB), 256>>>(entities, mentions, W_h, b_h, W_t, b_t);
    k_mid<<<400, 256>>>(W_h, W_t);
    k_out2<<<dim3(EE, BB, 4), 256>>>(b_h, b_t, out);
}

// round 6
// speedup vs baseline: 1.4740x; 1.0514x over previous
#include <cuda_runtime.h>

#define BB 8
#define EE 64
#define MM 128
#define DD 256
#define HH 8
#define DKK 32
#define NPAIR (EE*EE)
#define SETHALF (BB*NPAIR*DD)

typedef unsigned long long ull;

// ---- packed fp32x2 helpers ----
__device__ __forceinline__ void fma2(ull &d, ull a, ull b) {
    asm("fma.rn.f32x2 %0, %1, %2, %0;" : "+l"(d) : "l"(a), "l"(b));
}
__device__ __forceinline__ ull bcast2(float x) {
    ull d;
    asm("mov.b64 %0, {%1, %1};" : "=l"(d) : "r"(__float_as_uint(x)));
    return d;
}
__device__ __forceinline__ float2 unpack2(ull v) {
    float2 r;
    asm("mov.b64 {%0, %1}, %2;" : "=f"(r.x), "=f"(r.y) : "l"(v));
    return r;
}

// ---------------- scratch ----------------
__device__ float g_q[2][BB*EE*DD];
__device__ float g_k[2][BB*MM*DD];
__device__ float g_v[2][BB*MM*DD];
__device__ float g_u[2][BB*HH*MM*DD];
__device__ float g_S[2][BB*HH*MM*EE];    // TRANSPOSED: [s][b][h][m][j]  (j innermost)
__device__ float g_usum[2][BB*DD];
__device__ int   g_cnt[BB*EE];
__device__ int   g_list[BB*EE*MM];

// ------- six projections (jobs 2,3 gather A from sentences via sent_ids) + lists ----
// grid (2, 11, 8): y in 0..9 = gemm tiles; y==10 (colTile 0) = list building.
__global__ __launch_bounds__(256) void k_gemm_all(
    const float* __restrict__ entities, const float* __restrict__ mentions,
    const float* __restrict__ sentences, const int* __restrict__ sent_ids,
    const int* __restrict__ eid,
    const float* __restrict__ W_h, const float* __restrict__ b_h,
    const float* __restrict__ W_t, const float* __restrict__ b_t)
{
    __shared__ float a_sh[32][68];
    __shared__ float w_sh[32][128];
    int b = blockIdx.z;
    int y = blockIdx.y;
    int colTile = blockIdx.x;
    int tid = threadIdx.x;

    if (y == 10) {
        if (colTile == 0 && tid < EE) {
            int e = tid;
            int cnt = 0;
            for (int m = 0; m < MM; m++)
                if (eid[b*MM + m] == e) g_list[(b*EE + e)*MM + cnt++] = m;
            g_cnt[b*EE + e] = cnt;
        }
        return;
    }

    int job, rowTile;
    if (y < 2) { job = y; rowTile = 0; }
    else       { job = 2 + ((y - 2) >> 1); rowTile = (y - 2) & 1; }
    const float* A; const float* W; const float* bias; float* C; int rows;
    bool indirect = false;
    switch (job) {
      case 0:  A = entities; W = W_h;          bias = b_h;       C = g_q[0]; rows = EE; break;
      case 1:  A = entities; W = W_t;          bias = b_t;       C = g_q[1]; rows = EE; break;
      case 2:  A = nullptr;  W = W_h + 65536;  bias = b_h + 256; C = g_k[0]; rows = MM; indirect = true; break;
      case 3:  A = nullptr;  W = W_t + 65536;  bias = b_t + 256; C = g_k[1]; rows = MM; indirect = true; break;
      case 4:  A = mentions; W = W_h + 131072; bias = b_h + 512; C = g_v[0]; rows = MM; break;
      default: A = mentions; W = W_t + 131072; bias = b_t + 512; C = g_v[1]; rows = MM; break;
    }
    int row0 = rowTile * 64;
    int col0 = colTile * 128;

    // per-thread A row pointers (constant across k); jobs 2/3 gather from sentences
    const float* rp[2];
    #pragma unroll
    for (int i = 0; i < 2; i++) {
        int f = tid * 2 + i;
        int r = f >> 3;
        int kq = (f & 7) * 4;
        if (indirect) {
            int sid = sent_ids[b * MM + row0 + r];
            rp[i] = sentences + ((size_t)(b * 32 + sid)) * DD + kq;
        } else {
            rp[i] = A + ((size_t)b * rows + row0 + r) * DD + kq;
        }
    }

    int rg = tid & 7;
    int cg = tid >> 3;
    ull acc[4][4];
    #pragma unroll
    for (int p = 0; p < 4; p++)
        #pragma unroll
        for (int c = 0; c < 4; c++) acc[p][c] = 0ull;

    for (int kc = 0; kc < 8; kc++) {
        int k0 = kc * 32;
        #pragma unroll
        for (int i = 0; i < 2; i++) {
            int f = tid * 2 + i;
            int r = f >> 3;
            int kq = (f & 7) * 4;
            float4 av = *(const float4*)(rp[i] + k0);
            a_sh[kq+0][r] = av.x; a_sh[kq+1][r] = av.y;
            a_sh[kq+2][r] = av.z; a_sh[kq+3][r] = av.w;
        }
        #pragma unroll
        for (int i = 0; i < 4; i++) {
            int idx = tid + i * 256;
            int kk = idx >> 5;
            int dq = (idx & 31) * 4;
            *(float4*)&w_sh[kk][dq] = *(const float4*)(W + (size_t)(k0 + kk) * DD + col0 + dq);
        }
        __syncthreads();
        #pragma unroll
        for (int kk = 0; kk < 32; kk++) {
            ulonglong2 A0 = *(const ulonglong2*)&a_sh[kk][rg * 8];
            ulonglong2 A1 = *(const ulonglong2*)&a_sh[kk][rg * 8 + 4];
            float4 wv = *(const float4*)&w_sh[kk][cg * 4];
            ull w0 = bcast2(wv.x), w1 = bcast2(wv.y), w2 = bcast2(wv.z), w3 = bcast2(wv.w);
            fma2(acc[0][0], A0.x, w0); fma2(acc[0][1], A0.x, w1);
            fma2(acc[0][2], A0.x, w2); fma2(acc[0][3], A0.x, w3);
            fma2(acc[1][0], A0.y, w0); fma2(acc[1][1], A0.y, w1);
            fma2(acc[1][2], A0.y, w2); fma2(acc[1][3], A0.y, w3);
            fma2(acc[2][0], A1.x, w0); fma2(acc[2][1], A1.x, w1);
            fma2(acc[2][2], A1.x, w2); fma2(acc[2][3], A1.x, w3);
            fma2(acc[3][0], A1.y, w0); fma2(acc[3][1], A1.y, w1);
            fma2(acc[3][2], A1.y, w2); fma2(acc[3][3], A1.y, w3);
        }
        __syncthreads();
    }
    float4 bi = *(const float4*)(bias + col0 + cg * 4);
    #pragma unroll
    for (int p = 0; p < 4; p++) {
        float2 c0 = unpack2(acc[p][0]), c1 = unpack2(acc[p][1]);
        float2 c2 = unpack2(acc[p][2]), c3 = unpack2(acc[p][3]);
        int re = row0 + rg * 8 + 2 * p;
        float4 oe = make_float4(c0.x + bi.x, c1.x + bi.y, c2.x + bi.z, c3.x + bi.w);
        float4 oo = make_float4(c0.y + bi.x, c1.y + bi.y, c2.y + bi.z, c3.y + bi.w);
        *(float4*)(C + ((size_t)b * rows + re)     * DD + col0 + cg * 4) = oe;
        *(float4*)(C + ((size_t)b * rows + re + 1) * DD + col0 + cg * 4) = oo;
    }
}

// ---------------- mid: uproj (256 blks) + usum (16 blks) + scores (128 blks) --------
__global__ __launch_bounds__(256) void k_mid(const float* __restrict__ W_h,
                                             const float* __restrict__ W_t)
{
    __shared__ __align__(16) char buf[33792];
    int blk = blockIdx.x;
    int tid = threadIdx.x;

    if (blk < 256) {
        int ct = blk & 1;
        int g = blk >> 1;
        int s = g >> 6, b = (g >> 3) & 7, h = g & 7;
        const float* Wo = (s ? W_t : W_h) + 3 * 65536 + h * DKK * DD;
        const float* V = g_v[s] + (size_t)b * MM * DD + h * DKK;
        int col0 = ct * 128;
        float (*a_sh)[132] = (float(*)[132])buf;
        float (*w_sh)[128] = (float(*)[128])(buf + 16896);

        #pragma unroll
        for (int i = 0; i < 4; i++) {
            int f = tid + i * 256;
            int r = f >> 3;
            int kq = (f & 7) * 4;
            float4 av = *(const float4*)(V + (size_t)r * DD + kq);
            a_sh[kq+0][r] = av.x; a_sh[kq+1][r] = av.y;
            a_sh[kq+2][r] = av.z; a_sh[kq+3][r] = av.w;
        }
        #pragma unroll
        for (int i = 0; i < 4; i++) {
            int idx = tid + i * 256;
            int kk = idx >> 5;
            int dq = (idx & 31) * 4;
            *(float4*)&w_sh[kk][dq] = *(const float4*)(Wo + (size_t)kk * DD + col0 + dq);
        }
        __syncthreads();

        int rg = tid & 15;
        int cg = tid >> 4;
        ull acc[4][8];
        #pragma unroll
        for (int p = 0; p < 4; p++)
            #pragma unroll
            for (int c = 0; c < 8; c++) acc[p][c] = 0ull;
        #pragma unroll
        for (int kk = 0; kk < 32; kk++) {
            ulonglong2 A0 = *(const ulonglong2*)&a_sh[kk][rg * 8];
            ulonglong2 A1 = *(const ulonglong2*)&a_sh[kk][rg * 8 + 4];
            float4 wa = *(const float4*)&w_sh[kk][cg * 8];
            float4 wb = *(const float4*)&w_sh[kk][cg * 8 + 4];
            ull wp[8] = { bcast2(wa.x), bcast2(wa.y), bcast2(wa.z), bcast2(wa.w),
                          bcast2(wb.x), bcast2(wb.y), bcast2(wb.z), bcast2(wb.w) };
            #pragma unroll
            for (int c = 0; c < 8; c++) {
                fma2(acc[0][c], A0.x, wp[c]);
                fma2(acc[1][c], A0.y, wp[c]);
                fma2(acc[2][c], A1.x, wp[c]);
                fma2(acc[3][c], A1.y, wp[c]);
            }
        }
        float* U = g_u[s] + ((size_t)(b * HH + h) * MM) * DD;
        #pragma unroll
        for (int p = 0; p < 4; p++) {
            float2 u0 = unpack2(acc[p][0]), u1 = unpack2(acc[p][1]);
            float2 u2 = unpack2(acc[p][2]), u3 = unpack2(acc[p][3]);
            float2 u4 = unpack2(acc[p][4]), u5 = unpack2(acc[p][5]);
            float2 u6 = unpack2(acc[p][6]), u7 = unpack2(acc[p][7]);
            int re = rg * 8 + 2 * p;
            float* d0 = U + (size_t)re * DD + col0 + cg * 8;
            float* d1 = d0 + DD;
            *(float4*)(d0)     = make_float4(u0.x, u1.x, u2.x, u3.x);
            *(float4*)(d0 + 4) = make_float4(u4.x, u5.x, u6.x, u7.x);
            *(float4*)(d1)     = make_float4(u0.y, u1.y, u2.y, u3.y);
            *(float4*)(d1 + 4) = make_float4(u4.y, u5.y, u6.y, u7.y);
        }
    } else if (blk < 272) {
        int id = blk - 256;
        int b = id & 7, s = id >> 3;
        const float* Wo = (s ? W_t : W_h) + 3 * 65536;
        float* vs = (float*)buf;
        int d = tid;
        const float* v = g_v[s] + (size_t)b * MM * DD;
        float sum = 0.f;
        for (int m = 0; m < MM; m++) sum += v[m * DD + d];
        vs[d] = sum;
        __syncthreads();
        float o = 0.f;
        for (int k = 0; k < DD; k++) o = fmaf(vs[k], Wo[(size_t)k * DD + d], o);
        g_usum[s][b * DD + d] = o;
    } else {
        // scores, TRANSPOSED output: S[s][b][h][m][j]
        int t = blk - 272;
        int h = t & 7, b = (t >> 3) & 7, s = t >> 6;
        float (*qs)[DKK + 1] = (float(*)[DKK + 1])buf;
        float (*ks)[DKK + 1] = (float(*)[DKK + 1])(buf + EE * (DKK + 1) * 4);
        const float* q = g_q[s] + (size_t)b * EE * DD + h * DKK;
        const float* k = g_k[s] + (size_t)b * MM * DD + h * DKK;
        for (int i = tid; i < EE * DKK; i += 256) { int r = i >> 5, c = i & 31; qs[r][c] = q[r * DD + c]; }
        for (int i = tid; i < MM * DKK; i += 256) { int r = i >> 5, c = i & 31; ks[r][c] = k[r * DD + c]; }
        __syncthreads();
        int j = tid & 63;
        int m0 = tid >> 6;
        float* Sbase = g_S[s] + (size_t)(b * HH + h) * MM * EE;
        const float scale = 0.17677669529663687f;
        for (int m = m0; m < MM; m += 4) {
            float acc = 0.f;
            #pragma unroll
            for (int c = 0; c < DKK; c++) acc = fmaf(qs[j][c], ks[m][c], acc);
            Sbase[(size_t)m * EE + j] = acc * scale;   // coalesced in j
        }
    }
}

// -------- fused output v3: j-split, 4 blocks/SM, u staged in smem, one sync/chunk ---
__global__ __launch_bounds__(256, 4) void k_out3(const float* __restrict__ b_h,
                                                 const float* __restrict__ b_t,
                                                 float* __restrict__ out)
{
    int i = blockIdx.x;
    int b = blockIdx.y;
    int z = blockIdx.z;
    int s = z >> 1;
    int j0 = (z & 1) * 32;
    const float* bo = (s ? b_t : b_h) + 3 * 256;
    float* outS = out + (size_t)s * SETHALF + (size_t)b * NPAIR * DD;
    int tid = threadIdx.x;
    int cnt = g_cnt[b * EE + i];

    if (cnt == 0) {
        const float* us = g_usum[s] + b * DD;
        for (int idx = tid; idx < 32 * 64; idx += 256) {
            int j = j0 + (idx >> 6);
            int q = idx & 63;
            float4 bo4 = *(const float4*)(bo + q * 4);
            float4 u4 = *(const float4*)(us + q * 4);
            float4 o = make_float4(bo4.x + u4.x * (1.0f/128.0f),
                                   bo4.y + u4.y * (1.0f/128.0f),
                                   bo4.z + u4.z * (1.0f/128.0f),
                                   bo4.w + u4.w * (1.0f/128.0f));
            int pair = (s == 0) ? (i * EE + j) : (j * EE + i);
            *(float4*)(outS + (size_t)pair * DD + q * 4) = o;
        }
        return;
    }

    __shared__ int lst[MM];
    __shared__ float mx[HH][32];
    __shared__ float rs[HH][32];
    __shared__ float wsh[HH][4][32];
    __shared__ float4 sU[HH][4][64];   // 32 KB: staged u rows for one chunk

    for (int t = tid; t < cnt; t += 256) lst[t] = g_list[(b * EE + i) * MM + t];
    __syncthreads();

    const float* Sb = g_S[s] + (size_t)(b * HH) * MM * EE;

    // stats: one (h, jl) per thread; coalesced 128B S-row reads
    {
        int h = tid >> 5;
        int jl = tid & 31;
        const float* Sh = Sb + (size_t)h * MM * EE + j0 + jl;
        float m_ = -1e30f;
        for (int c = 0; c < cnt; c++) m_ = fmaxf(m_, Sh[(size_t)lst[c] * EE]);
        float se = 0.f;
        for (int c = 0; c < cnt; c++) se += __expf(Sh[(size_t)lst[c] * EE] - m_);
        mx[h][jl] = m_;
        rs[h][jl] = 1.0f / se;
    }
    __syncthreads();

    int dq = tid & 63;    // d = dq*4 .. dq*4+3
    int jg = tid >> 6;    // j = j0 + jg*8 .. +7
    ull acc[8][2];
    #pragma unroll
    for (int jj = 0; jj < 8; jj++) { acc[jj][0] = 0ull; acc[jj][1] = 0ull; }

    const float* Ug = g_u[s] + (size_t)(b * HH) * MM * DD;

    for (int base = 0; base < cnt; base += 4) {
        int ce = min(4, cnt - base);
        // stage u rows: 8 independent float4 LDGs per thread (MLP=8), coalesced
        #pragma unroll
        for (int rr = 0; rr < 8; rr++) {
            int t = tid + rr * 256;            // t < 2048
            int h = t >> 8, c = (t >> 6) & 3, q = t & 63;
            if (c < ce)
                sU[h][c][q] = *(const float4*)(Ug + ((size_t)h * MM + lst[base + c]) * DD + q * 4);
        }
        // weights (independent of the u loads above): coalesced S reads + exp
        for (int t = tid; t < HH * 4 * 32; t += 256) {
            int h = t >> 7, c = (t >> 5) & 3, jl = t & 31;
            if (c < ce) {
                float sv = Sb[((size_t)h * MM + lst[base + c]) * EE + j0 + jl];
                wsh[h][c][jl] = __expf(sv - mx[h][jl]) * rs[h][jl];
            }
        }
        __syncthreads();
        for (int c = 0; c < ce; c++) {
            #pragma unroll
            for (int h = 0; h < HH; h++) {
                ulonglong2 U = *(const ulonglong2*)&sU[h][c][dq];  // conflict-free LDS.128
                const float* wr = &wsh[h][c][jg * 8];
                float4 wa = *(const float4*)(wr);                  // warp-broadcast
                float4 wb = *(const float4*)(wr + 4);
                ull w0 = bcast2(wa.x), w1 = bcast2(wa.y), w2 = bcast2(wa.z), w3 = bcast2(wa.w);
                fma2(acc[0][0], w0, U.x); fma2(acc[0][1], w0, U.y);
                fma2(acc[1][0], w1, U.x); fma2(acc[1][1], w1, U.y);
                fma2(acc[2][0], w2, U.x); fma2(acc[2][1], w2, U.y);
                fma2(acc[3][0], w3, U.x); fma2(acc[3][1], w3, U.y);
                ull w4 = bcast2(wb.x), w5 = bcast2(wb.y), w6 = bcast2(wb.z), w7 = bcast2(wb.w);
                fma2(acc[4][0], w4, U.x); fma2(acc[4][1], w4, U.y);
                fma2(acc[5][0], w5, U.x); fma2(acc[5][1], w5, U.y);
                fma2(acc[6][0], w6, U.x); fma2(acc[6][1], w6, U.y);
                fma2(acc[7][0], w7, U.x); fma2(acc[7][1], w7, U.y);
            }
        }
        __syncthreads();
    }

    float4 bo4 = *(const float4*)(bo + dq * 4);
    #pragma unroll
    for (int jj = 0; jj < 8; jj++) {
        int j = j0 + jg * 8 + jj;
        int pair = (s == 0) ? (i * EE + j) : (j * EE + i);
        float2 p0 = unpack2(acc[jj][0]);
        float2 p1 = unpack2(acc[jj][1]);
        float4 o = make_float4(p0.x + bo4.x, p0.y + bo4.y, p1.x + bo4.z, p1.y + bo4.w);
        *(float4*)(outS + (size_t)pair * DD + dq * 4) = o;
    }
}

// ---------------- launch ----------------
extern "C" void kernel_launch(void* const* d_in, const int* in_sizes, int n_in,
                              void* d_out, int out_size) {
    const float* entities  = (const float*)d_in[0];
    const float* mentions  = (const float*)d_in[1];
    const float* sentences = (const float*)d_in[2];
    const int*   sent_ids  = (const int*)d_in[3];
    const int*   eid       = (const int*)d_in[4];
    const float* W_h       = (const float*)d_in[5];
    const float* b_h       = (const float*)d_in[6];
    const float* W_t       = (const float*)d_in[7];
    const float* b_t       = (const float*)d_in[8];
    float* out = (float*)d_out;

    k_gemm_all<<<dim3(2, 11, BB), 256>>>(entities, mentions, sentences, sent_ids, eid,
                                         W_h, b_h, W_t, b_t);
    k_mid<<<400, 256>>>(W_h, W_t);
    k_out3<<<dim3(EE, BB, 4), 256>>>(b_h, b_t, out);
}

// round 7
// speedup vs baseline: 1.7818x; 1.2088x over previous
#include <cuda_runtime.h>

#define BB 8
#define EE 64
#define MM 128
#define DD 256
#define HH 8
#define DKK 32
#define NPAIR (EE*EE)
#define SETHALF (BB*NPAIR*DD)

typedef unsigned long long ull;

// ---- packed fp32x2 helpers ----
__device__ __forceinline__ void fma2(ull &d, ull a, ull b) {
    asm("fma.rn.f32x2 %0, %1, %2, %0;" : "+l"(d) : "l"(a), "l"(b));
}
__device__ __forceinline__ ull bcast2(float x) {
    ull d;
    asm("mov.b64 %0, {%1, %1};" : "=l"(d) : "r"(__float_as_uint(x)));
    return d;
}
__device__ __forceinline__ float2 unpack2(ull v) {
    float2 r;
    asm("mov.b64 {%0, %1}, %2;" : "=f"(r.x), "=f"(r.y) : "l"(v));
    return r;
}

// ---------------- scratch ----------------
__device__ float g_q[2][BB*EE*DD];
__device__ float g_k[2][BB*MM*DD];
__device__ float g_v[2][BB*MM*DD];
__device__ float g_u[2][BB*HH*MM*DD];
__device__ float g_S[2][BB*HH*MM*EE];    // TRANSPOSED: [s][b][h][m][j]  (j innermost)
__device__ float g_usum[2][BB*DD];
__device__ int   g_cnt[BB*EE];
__device__ int   g_list[BB*EE*MM];

// ------- six projections, 64x64 tiles, 4x4/thread, prefetched, 4 blocks/SM ---------
// grid (4, 11, 8): y in 0..9 = gemm jobs/rowTiles; y==10 & x==0 = list building.
__global__ __launch_bounds__(256, 4) void k_gemm_all(
    const float* __restrict__ entities, const float* __restrict__ mentions,
    const float* __restrict__ sentences, const int* __restrict__ sent_ids,
    const int* __restrict__ eid,
    const float* __restrict__ W_h, const float* __restrict__ b_h,
    const float* __restrict__ W_t, const float* __restrict__ b_t)
{
    __shared__ float a_sh[32][68];   // [k][row] transposed, 64 rows + pad
    __shared__ float w_sh[32][64];   // [k][col]
    int b = blockIdx.z;
    int y = blockIdx.y;
    int colTile = blockIdx.x;
    int tid = threadIdx.x;

    if (y == 10) {
        if (colTile == 0 && tid < EE) {
            int e = tid;
            int cnt = 0;
            for (int m = 0; m < MM; m++)
                if (eid[b*MM + m] == e) g_list[(b*EE + e)*MM + cnt++] = m;
            g_cnt[b*EE + e] = cnt;
        }
        return;
    }

    int job, rowTile;
    if (y < 2) { job = y; rowTile = 0; }
    else       { job = 2 + ((y - 2) >> 1); rowTile = (y - 2) & 1; }
    const float* A; const float* W; const float* bias; float* C; int rows;
    bool indirect = false;
    switch (job) {
      case 0:  A = entities; W = W_h;          bias = b_h;       C = g_q[0]; rows = EE; break;
      case 1:  A = entities; W = W_t;          bias = b_t;       C = g_q[1]; rows = EE; break;
      case 2:  A = nullptr;  W = W_h + 65536;  bias = b_h + 256; C = g_k[0]; rows = MM; indirect = true; break;
      case 3:  A = nullptr;  W = W_t + 65536;  bias = b_t + 256; C = g_k[1]; rows = MM; indirect = true; break;
      case 4:  A = mentions; W = W_h + 131072; bias = b_h + 512; C = g_v[0]; rows = MM; break;
      default: A = mentions; W = W_t + 131072; bias = b_t + 512; C = g_v[1]; rows = MM; break;
    }
    int row0 = rowTile * 64;
    int col0 = colTile * 64;

    // staging indices (A: 512 float4, 2/thread; W: 512 float4, 2/thread)
    int rI[2], kqI[2], kkI[2], dqI[2];
    const float* rp[2];
    const float* wp[2];
    #pragma unroll
    for (int i = 0; i < 2; i++) {
        int f = tid * 2 + i;
        rI[i] = f >> 3;
        kqI[i] = (f & 7) * 4;
        if (indirect) {
            int sid = sent_ids[b * MM + row0 + rI[i]];
            rp[i] = sentences + ((size_t)(b * 32 + sid)) * DD + kqI[i];
        } else {
            rp[i] = A + ((size_t)b * rows + row0 + rI[i]) * DD + kqI[i];
        }
        int idx = tid + i * 256;
        kkI[i] = idx >> 4;
        dqI[i] = (idx & 15) * 4;
        wp[i] = W + (size_t)kkI[i] * DD + col0 + dqI[i];
    }

    int rg = tid & 15;    // 16 row groups x 4 rows
    int cg = tid >> 4;    // 16 col groups x 4 cols
    ull acc[2][4];
    #pragma unroll
    for (int p = 0; p < 2; p++)
        #pragma unroll
        for (int c = 0; c < 4; c++) acc[p][c] = 0ull;

    // prefetch kc=0
    float4 pa[2], pw[2];
    #pragma unroll
    for (int i = 0; i < 2; i++) { pa[i] = *(const float4*)(rp[i]); pw[i] = *(const float4*)(wp[i]); }

    for (int kc = 0; kc < 8; kc++) {
        // commit staged tiles to smem
        #pragma unroll
        for (int i = 0; i < 2; i++) {
            a_sh[kqI[i]+0][rI[i]] = pa[i].x; a_sh[kqI[i]+1][rI[i]] = pa[i].y;
            a_sh[kqI[i]+2][rI[i]] = pa[i].z; a_sh[kqI[i]+3][rI[i]] = pa[i].w;
            *(float4*)&w_sh[kkI[i]][dqI[i]] = pw[i];
        }
        __syncthreads();
        // issue next-kc loads early (latency overlapped with compute below)
        if (kc < 7) {
            int k0n = (kc + 1) * 32;
            #pragma unroll
            for (int i = 0; i < 2; i++) {
                pa[i] = *(const float4*)(rp[i] + k0n);
                pw[i] = *(const float4*)(wp[i] + (size_t)k0n * DD);
            }
        }
        #pragma unroll
        for (int kk = 0; kk < 32; kk++) {
            ulonglong2 Av = *(const ulonglong2*)&a_sh[kk][rg * 4];  // rows (0,1),(2,3)
            float4 wv = *(const float4*)&w_sh[kk][cg * 4];
            ull w0 = bcast2(wv.x), w1 = bcast2(wv.y), w2 = bcast2(wv.z), w3 = bcast2(wv.w);
            fma2(acc[0][0], Av.x, w0); fma2(acc[0][1], Av.x, w1);
            fma2(acc[0][2], Av.x, w2); fma2(acc[0][3], Av.x, w3);
            fma2(acc[1][0], Av.y, w0); fma2(acc[1][1], Av.y, w1);
            fma2(acc[1][2], Av.y, w2); fma2(acc[1][3], Av.y, w3);
        }
        __syncthreads();
    }

    float4 bi = *(const float4*)(bias + col0 + cg * 4);
    #pragma unroll
    for (int p = 0; p < 2; p++) {
        float2 c0 = unpack2(acc[p][0]), c1 = unpack2(acc[p][1]);
        float2 c2 = unpack2(acc[p][2]), c3 = unpack2(acc[p][3]);
        int re = row0 + rg * 4 + 2 * p;
        float4 oe = make_float4(c0.x + bi.x, c1.x + bi.y, c2.x + bi.z, c3.x + bi.w);
        float4 oo = make_float4(c0.y + bi.x, c1.y + bi.y, c2.y + bi.z, c3.y + bi.w);
        *(float4*)(C + ((size_t)b * rows + re)     * DD + col0 + cg * 4) = oe;
        *(float4*)(C + ((size_t)b * rows + re + 1) * DD + col0 + cg * 4) = oo;
    }
}

// ---------------- mid: uproj (256 blks) + usum (16 blks) + scores (128 blks) --------
__global__ __launch_bounds__(256) void k_mid(const float* __restrict__ W_h,
                                             const float* __restrict__ W_t)
{
    __shared__ __align__(16) char buf[33792];
    int blk = blockIdx.x;
    int tid = threadIdx.x;

    if (blk < 256) {
        int ct = blk & 1;
        int g = blk >> 1;
        int s = g >> 6, b = (g >> 3) & 7, h = g & 7;
        const float* Wo = (s ? W_t : W_h) + 3 * 65536 + h * DKK * DD;
        const float* V = g_v[s] + (size_t)b * MM * DD + h * DKK;
        int col0 = ct * 128;
        float (*a_sh)[132] = (float(*)[132])buf;
        float (*w_sh)[128] = (float(*)[128])(buf + 16896);

        #pragma unroll
        for (int i = 0; i < 4; i++) {
            int f = tid + i * 256;
            int r = f >> 3;
            int kq = (f & 7) * 4;
            float4 av = *(const float4*)(V + (size_t)r * DD + kq);
            a_sh[kq+0][r] = av.x; a_sh[kq+1][r] = av.y;
            a_sh[kq+2][r] = av.z; a_sh[kq+3][r] = av.w;
        }
        #pragma unroll
        for (int i = 0; i < 4; i++) {
            int idx = tid + i * 256;
            int kk = idx >> 5;
            int dq = (idx & 31) * 4;
            *(float4*)&w_sh[kk][dq] = *(const float4*)(Wo + (size_t)kk * DD + col0 + dq);
        }
        __syncthreads();

        int rg = tid & 15;
        int cg = tid >> 4;
        ull acc[4][8];
        #pragma unroll
        for (int p = 0; p < 4; p++)
            #pragma unroll
            for (int c = 0; c < 8; c++) acc[p][c] = 0ull;
        #pragma unroll
        for (int kk = 0; kk < 32; kk++) {
            ulonglong2 A0 = *(const ulonglong2*)&a_sh[kk][rg * 8];
            ulonglong2 A1 = *(const ulonglong2*)&a_sh[kk][rg * 8 + 4];
            float4 wa = *(const float4*)&w_sh[kk][cg * 8];
            float4 wb = *(const float4*)&w_sh[kk][cg * 8 + 4];
            ull wp[8] = { bcast2(wa.x), bcast2(wa.y), bcast2(wa.z), bcast2(wa.w),
                          bcast2(wb.x), bcast2(wb.y), bcast2(wb.z), bcast2(wb.w) };
            #pragma unroll
            for (int c = 0; c < 8; c++) {
                fma2(acc[0][c], A0.x, wp[c]);
                fma2(acc[1][c], A0.y, wp[c]);
                fma2(acc[2][c], A1.x, wp[c]);
                fma2(acc[3][c], A1.y, wp[c]);
            }
        }
        float* U = g_u[s] + ((size_t)(b * HH + h) * MM) * DD;
        #pragma unroll
        for (int p = 0; p < 4; p++) {
            float2 u0 = unpack2(acc[p][0]), u1 = unpack2(acc[p][1]);
            float2 u2 = unpack2(acc[p][2]), u3 = unpack2(acc[p][3]);
            float2 u4 = unpack2(acc[p][4]), u5 = unpack2(acc[p][5]);
            float2 u6 = unpack2(acc[p][6]), u7 = unpack2(acc[p][7]);
            int re = rg * 8 + 2 * p;
            float* d0 = U + (size_t)re * DD + col0 + cg * 8;
            float* d1 = d0 + DD;
            *(float4*)(d0)     = make_float4(u0.x, u1.x, u2.x, u3.x);
            *(float4*)(d0 + 4) = make_float4(u4.x, u5.x, u6.x, u7.x);
            *(float4*)(d1)     = make_float4(u0.y, u1.y, u2.y, u3.y);
            *(float4*)(d1 + 4) = make_float4(u4.y, u5.y, u6.y, u7.y);
        }
    } else if (blk < 272) {
        int id = blk - 256;
        int b = id & 7, s = id >> 3;
        const float* Wo = (s ? W_t : W_h) + 3 * 65536;
        float* vs = (float*)buf;
        int d = tid;
        const float* v = g_v[s] + (size_t)b * MM * DD;
        float sum = 0.f;
        for (int m = 0; m < MM; m++) sum += v[m * DD + d];
        vs[d] = sum;
        __syncthreads();
        float o = 0.f;
        for (int k = 0; k < DD; k++) o = fmaf(vs[k], Wo[(size_t)k * DD + d], o);
        g_usum[s][b * DD + d] = o;
    } else {
        // scores, TRANSPOSED output: S[s][b][h][m][j]
        int t = blk - 272;
        int h = t & 7, b = (t >> 3) & 7, s = t >> 6;
        float (*qs)[DKK + 1] = (float(*)[DKK + 1])buf;
        float (*ks)[DKK + 1] = (float(*)[DKK + 1])(buf + EE * (DKK + 1) * 4);
        const float* q = g_q[s] + (size_t)b * EE * DD + h * DKK;
        const float* k = g_k[s] + (size_t)b * MM * DD + h * DKK;
        for (int i = tid; i < EE * DKK; i += 256) { int r = i >> 5, c = i & 31; qs[r][c] = q[r * DD + c]; }
        for (int i = tid; i < MM * DKK; i += 256) { int r = i >> 5, c = i & 31; ks[r][c] = k[r * DD + c]; }
        __syncthreads();
        int j = tid & 63;
        int m0 = tid >> 6;
        float* Sbase = g_S[s] + (size_t)(b * HH + h) * MM * EE;
        const float scale = 0.17677669529663687f;
        for (int m = m0; m < MM; m += 4) {
            float acc = 0.f;
            #pragma unroll
            for (int c = 0; c < DKK; c++) acc = fmaf(qs[j][c], ks[m][c], acc);
            Sbase[(size_t)m * EE + j] = acc * scale;   // coalesced in j
        }
    }
}

// -------- fused output v3: j-split, 4 blocks/SM, u staged in smem, one sync/chunk ---
__global__ __launch_bounds__(256, 4) void k_out3(const float* __restrict__ b_h,
                                                 const float* __restrict__ b_t,
                                                 float* __restrict__ out)
{
    int i = blockIdx.x;
    int b = blockIdx.y;
    int z = blockIdx.z;
    int s = z >> 1;
    int j0 = (z & 1) * 32;
    const float* bo = (s ? b_t : b_h) + 3 * 256;
    float* outS = out + (size_t)s * SETHALF + (size_t)b * NPAIR * DD;
    int tid = threadIdx.x;
    int cnt = g_cnt[b * EE + i];

    if (cnt == 0) {
        const float* us = g_usum[s] + b * DD;
        for (int idx = tid; idx < 32 * 64; idx += 256) {
            int j = j0 + (idx >> 6);
            int q = idx & 63;
            float4 bo4 = *(const float4*)(bo + q * 4);
            float4 u4 = *(const float4*)(us + q * 4);
            float4 o = make_float4(bo4.x + u4.x * (1.0f/128.0f),
                                   bo4.y + u4.y * (1.0f/128.0f),
                                   bo4.z + u4.z * (1.0f/128.0f),
                                   bo4.w + u4.w * (1.0f/128.0f));
            int pair = (s == 0) ? (i * EE + j) : (j * EE + i);
            *(float4*)(outS + (size_t)pair * DD + q * 4) = o;
        }
        return;
    }

    __shared__ int lst[MM];
    __shared__ float mx[HH][32];
    __shared__ float rs[HH][32];
    __shared__ float wsh[HH][4][32];
    __shared__ float4 sU[HH][4][64];   // 32 KB: staged u rows for one chunk

    for (int t = tid; t < cnt; t += 256) lst[t] = g_list[(b * EE + i) * MM + t];
    __syncthreads();

    const float* Sb = g_S[s] + (size_t)(b * HH) * MM * EE;

    // stats: one (h, jl) per thread; coalesced 128B S-row reads
    {
        int h = tid >> 5;
        int jl = tid & 31;
        const float* Sh = Sb + (size_t)h * MM * EE + j0 + jl;
        float m_ = -1e30f;
        for (int c = 0; c < cnt; c++) m_ = fmaxf(m_, Sh[(size_t)lst[c] * EE]);
        float se = 0.f;
        for (int c = 0; c < cnt; c++) se += __expf(Sh[(size_t)lst[c] * EE] - m_);
        mx[h][jl] = m_;
        rs[h][jl] = 1.0f / se;
    }
    __syncthreads();

    int dq = tid & 63;    // d = dq*4 .. dq*4+3
    int jg = tid >> 6;    // j = j0 + jg*8 .. +7
    ull acc[8][2];
    #pragma unroll
    for (int jj = 0; jj < 8; jj++) { acc[jj][0] = 0ull; acc[jj][1] = 0ull; }

    const float* Ug = g_u[s] + (size_t)(b * HH) * MM * DD;

    for (int base = 0; base < cnt; base += 4) {
        int ce = min(4, cnt - base);
        // stage u rows: 8 independent float4 LDGs per thread (MLP=8), coalesced
        #pragma unroll
        for (int rr = 0; rr < 8; rr++) {
            int t = tid + rr * 256;            // t < 2048
            int h = t >> 8, c = (t >> 6) & 3, q = t & 63;
            if (c < ce)
                sU[h][c][q] = *(const float4*)(Ug + ((size_t)h * MM + lst[base + c]) * DD + q * 4);
        }
        // weights (independent of the u loads above): coalesced S reads + exp
        for (int t = tid; t < HH * 4 * 32; t += 256) {
            int h = t >> 7, c = (t >> 5) & 3, jl = t & 31;
            if (c < ce) {
                float sv = Sb[((size_t)h * MM + lst[base + c]) * EE + j0 + jl];
                wsh[h][c][jl] = __expf(sv - mx[h][jl]) * rs[h][jl];
            }
        }
        __syncthreads();
        for (int c = 0; c < ce; c++) {
            #pragma unroll
            for (int h = 0; h < HH; h++) {
                ulonglong2 U = *(const ulonglong2*)&sU[h][c][dq];  // conflict-free LDS.128
                const float* wr = &wsh[h][c][jg * 8];
                float4 wa = *(const float4*)(wr);                  // warp-broadcast
                float4 wb = *(const float4*)(wr + 4);
                ull w0 = bcast2(wa.x), w1 = bcast2(wa.y), w2 = bcast2(wa.z), w3 = bcast2(wa.w);
                fma2(acc[0][0], w0, U.x); fma2(acc[0][1], w0, U.y);
                fma2(acc[1][0], w1, U.x); fma2(acc[1][1], w1, U.y);
                fma2(acc[2][0], w2, U.x); fma2(acc[2][1], w2, U.y);
                fma2(acc[3][0], w3, U.x); fma2(acc[3][1], w3, U.y);
                ull w4 = bcast2(wb.x), w5 = bcast2(wb.y), w6 = bcast2(wb.z), w7 = bcast2(wb.w);
                fma2(acc[4][0], w4, U.x); fma2(acc[4][1], w4, U.y);
                fma2(acc[5][0], w5, U.x); fma2(acc[5][1], w5, U.y);
                fma2(acc[6][0], w6, U.x); fma2(acc[6][1], w6, U.y);
                fma2(acc[7][0], w7, U.x); fma2(acc[7][1], w7, U.y);
            }
        }
        __syncthreads();
    }

    float4 bo4 = *(const float4*)(bo + dq * 4);
    #pragma unroll
    for (int jj = 0; jj < 8; jj++) {
        int j = j0 + jg * 8 + jj;
        int pair = (s == 0) ? (i * EE + j) : (j * EE + i);
        float2 p0 = unpack2(acc[jj][0]);
        float2 p1 = unpack2(acc[jj][1]);
        float4 o = make_float4(p0.x + bo4.x, p0.y + bo4.y, p1.x + bo4.z, p1.y + bo4.w);
        *(float4*)(outS + (size_t)pair * DD + dq * 4) = o;
    }
}

// ---------------- launch ----------------
extern "C" void kernel_launch(void* const* d_in, const int* in_sizes, int n_in,
                              void* d_out, int out_size) {
    const float* entities  = (const float*)d_in[0];
    const float* mentions  = (const float*)d_in[1];
    const float* sentences = (const float*)d_in[2];
    const int*   sent_ids  = (const int*)d_in[3];
    const int*   eid       = (const int*)d_in[4];
    const float* W_h       = (const float*)d_in[5];
    const float* b_h       = (const float*)d_in[6];
    const float* W_t       = (const float*)d_in[7];
    const float* b_t       = (const float*)d_in[8];
    float* out = (float*)d_out;

    k_gemm_all<<<dim3(4, 11, BB), 256>>>(entities, mentions, sentences, sent_ids, eid,
                                         W_h, b_h, W_t, b_t);
    k_mid<<<400, 256>>>(W_h, W_t);
    k_out3<<<dim3(EE, BB, 4), 256>>>(b_h, b_t, out);
}